// round 1
// baseline (speedup 1.0000x reference)
#include <cuda_runtime.h>
#include <math.h>

// ---------------------------------------------------------------------------
// SelfAttention: out = softmax((xWq+bq)(xWk+bk)^T / sqrt(D)) (xWv+bv)
// B=4, S=2048, D=1024, fp32.
// Round 1: fp32 tiled SGEMM baseline (FFMA), scratch in __device__ globals.
// ---------------------------------------------------------------------------

#define BATCH 4
#define SEQ   2048
#define DIM   1024
#define ROWS  (BATCH * SEQ)          // 8192

#define BM 128
#define BN 128
#define BK 16
#define TM 8
#define TN 8

// Scratch (allocation-free rule: device globals)
__device__ float g_Q[(size_t)ROWS * DIM];          // 32 MB
__device__ float g_K[(size_t)ROWS * DIM];          // 32 MB
__device__ float g_V[(size_t)ROWS * DIM];          // 32 MB
__device__ float g_S[(size_t)BATCH * SEQ * SEQ];   // 64 MB

// Tiled SGEMM: C[z] = alpha * A[z] @ op(B[z]) (+ bias)
//   TRANSB=false: B is [K,N] row-major (NN)
//   TRANSB=true : B is [N,K] row-major (NT)
// M,N multiples of 128; K multiple of 16. 256 threads, 8x8 micro-tile.
template <bool TRANSB, bool BIAS>
__global__ __launch_bounds__(256, 2)
void sgemm128(const float* __restrict__ A, const float* __restrict__ B,
              const float* __restrict__ bias, float* __restrict__ C,
              int M, int N, int K, float alpha,
              int sA, int sB, int sC)
{
    __shared__ float As[BK][BM];
    __shared__ float Bs[BK][BN];

    const int tid = threadIdx.x;
    const int bm = blockIdx.y * BM;
    const int bn = blockIdx.x * BN;

    A += (size_t)blockIdx.z * sA;
    B += (size_t)blockIdx.z * sB;
    C += (size_t)blockIdx.z * sC;

    const int tr = tid >> 4;   // 0..15
    const int tc = tid & 15;   // 0..15

    float acc[TM][TN];
#pragma unroll
    for (int i = 0; i < TM; i++)
#pragma unroll
        for (int j = 0; j < TN; j++) acc[i][j] = 0.0f;

    for (int k0 = 0; k0 < K; k0 += BK) {
        // --- A tile: As[kk][m] = A[(bm+m)*K + k0+kk], float4 along K, transposed store
#pragma unroll
        for (int i = 0; i < 2; i++) {
            int idx = tid + i * 256;            // 0..511
            int m  = idx >> 2;                  // 0..127
            int kv = (idx & 3) << 2;            // 0,4,8,12
            float4 v = *(const float4*)(A + (size_t)(bm + m) * K + k0 + kv);
            As[kv + 0][m] = v.x; As[kv + 1][m] = v.y;
            As[kv + 2][m] = v.z; As[kv + 3][m] = v.w;
        }
        // --- B tile
        if (TRANSB) {
            // Bs[kk][n] = B[(bn+n)*K + k0+kk]
#pragma unroll
            for (int i = 0; i < 2; i++) {
                int idx = tid + i * 256;
                int n  = idx >> 2;
                int kv = (idx & 3) << 2;
                float4 v = *(const float4*)(B + (size_t)(bn + n) * K + k0 + kv);
                Bs[kv + 0][n] = v.x; Bs[kv + 1][n] = v.y;
                Bs[kv + 2][n] = v.z; Bs[kv + 3][n] = v.w;
            }
        } else {
            // Bs[kk][n] = B[(k0+kk)*N + bn+n], coalesced float4 along N
#pragma unroll
            for (int i = 0; i < 2; i++) {
                int idx = tid + i * 256;
                int kk = idx >> 5;              // 0..15
                int nv = (idx & 31) << 2;       // 0..124
                *(float4*)&Bs[kk][nv] =
                    *(const float4*)(B + (size_t)(k0 + kk) * N + bn + nv);
            }
        }
        __syncthreads();

#pragma unroll
        for (int kk = 0; kk < BK; kk++) {
            float af[TM], bf[TN];
            *(float4*)&af[0] = *(const float4*)&As[kk][tr * TM];
            *(float4*)&af[4] = *(const float4*)&As[kk][tr * TM + 4];
            *(float4*)&bf[0] = *(const float4*)&Bs[kk][tc * TN];
            *(float4*)&bf[4] = *(const float4*)&Bs[kk][tc * TN + 4];
#pragma unroll
            for (int i = 0; i < TM; i++)
#pragma unroll
                for (int j = 0; j < TN; j++)
                    acc[i][j] += af[i] * bf[j];
        }
        __syncthreads();
    }

    // --- epilogue: C = alpha*acc (+ bias), float4 stores
#pragma unroll
    for (int i = 0; i < TM; i++) {
        size_t row = (size_t)(bm + tr * TM + i) * N + bn + tc * TN;
#pragma unroll
        for (int j4 = 0; j4 < TN; j4 += 4) {
            float4 v;
            v.x = acc[i][j4 + 0] * alpha;
            v.y = acc[i][j4 + 1] * alpha;
            v.z = acc[i][j4 + 2] * alpha;
            v.w = acc[i][j4 + 3] * alpha;
            if (BIAS) {
                int col = bn + tc * TN + j4;
                v.x += bias[col + 0]; v.y += bias[col + 1];
                v.z += bias[col + 2]; v.w += bias[col + 3];
            }
            *(float4*)(C + row + j4) = v;
        }
    }
}

// In-place row softmax over rows of length 2048. One block (256 thr) per row.
__global__ __launch_bounds__(256)
void softmax2048(float* __restrict__ S)
{
    __shared__ float red_max[8];
    __shared__ float red_sum[8];

    float* p = S + (size_t)blockIdx.x * 2048;
    const int t = threadIdx.x;

    float4 v0 = ((const float4*)p)[t];
    float4 v1 = ((const float4*)p)[t + 256];

    float m = fmaxf(fmaxf(fmaxf(v0.x, v0.y), fmaxf(v0.z, v0.w)),
                    fmaxf(fmaxf(v1.x, v1.y), fmaxf(v1.z, v1.w)));
#pragma unroll
    for (int o = 16; o; o >>= 1)
        m = fmaxf(m, __shfl_xor_sync(0xffffffffu, m, o));
    if ((t & 31) == 0) red_max[t >> 5] = m;
    __syncthreads();
    m = red_max[0];
#pragma unroll
    for (int w = 1; w < 8; w++) m = fmaxf(m, red_max[w]);

    v0.x = expf(v0.x - m); v0.y = expf(v0.y - m);
    v0.z = expf(v0.z - m); v0.w = expf(v0.w - m);
    v1.x = expf(v1.x - m); v1.y = expf(v1.y - m);
    v1.z = expf(v1.z - m); v1.w = expf(v1.w - m);

    float s = (v0.x + v0.y + v0.z + v0.w) + (v1.x + v1.y + v1.z + v1.w);
#pragma unroll
    for (int o = 16; o; o >>= 1)
        s += __shfl_xor_sync(0xffffffffu, s, o);
    if ((t & 31) == 0) red_sum[t >> 5] = s;
    __syncthreads();
    s = red_sum[0];
#pragma unroll
    for (int w = 1; w < 8; w++) s += red_sum[w];

    float inv = 1.0f / s;
    v0.x *= inv; v0.y *= inv; v0.z *= inv; v0.w *= inv;
    v1.x *= inv; v1.y *= inv; v1.z *= inv; v1.w *= inv;

    ((float4*)p)[t]       = v0;
    ((float4*)p)[t + 256] = v1;
}

extern "C" void kernel_launch(void* const* d_in, const int* in_sizes, int n_in,
                              void* d_out, int out_size)
{
    (void)in_sizes; (void)n_in; (void)out_size;
    const float* x  = (const float*)d_in[0];
    const float* Wq = (const float*)d_in[1];
    const float* bq = (const float*)d_in[2];
    const float* Wk = (const float*)d_in[3];
    const float* bk = (const float*)d_in[4];
    const float* Wv = (const float*)d_in[5];
    const float* bv = (const float*)d_in[6];
    float* out = (float*)d_out;

    float *Q, *K, *V, *S;
    cudaGetSymbolAddress((void**)&Q, g_Q);
    cudaGetSymbolAddress((void**)&K, g_K);
    cudaGetSymbolAddress((void**)&V, g_V);
    cudaGetSymbolAddress((void**)&S, g_S);

    const float inv_sqrt_d = 0.03125f;  // 1/sqrt(1024)

    // 1) QKV projections: [8192,1024] x [1024,1024] (+bias)
    {
        dim3 grid(DIM / BN, ROWS / BM, 1);
        sgemm128<false, true><<<grid, 256>>>(x, Wq, bq, Q, ROWS, DIM, DIM, 1.0f, 0, 0, 0);
        sgemm128<false, true><<<grid, 256>>>(x, Wk, bk, K, ROWS, DIM, DIM, 1.0f, 0, 0, 0);
        sgemm128<false, true><<<grid, 256>>>(x, Wv, bv, V, ROWS, DIM, DIM, 1.0f, 0, 0, 0);
    }

    // 2) scores = Q @ K^T * (1/sqrt(D)), batched over 4
    {
        dim3 grid(SEQ / BN, SEQ / BM, BATCH);
        sgemm128<true, false><<<grid, 256>>>(Q, K, nullptr, S,
                                             SEQ, SEQ, DIM, inv_sqrt_d,
                                             SEQ * DIM, SEQ * DIM, SEQ * SEQ);
    }

    // 3) softmax rows (B*S rows of length S)
    softmax2048<<<BATCH * SEQ, 256>>>(S);

    // 4) out = P @ V, batched over 4
    {
        dim3 grid(DIM / BN, SEQ / BM, BATCH);
        sgemm128<false, false><<<grid, 256>>>(S, V, nullptr, out,
                                              SEQ, DIM, SEQ, 1.0f,
                                              SEQ * SEQ, SEQ * DIM, SEQ * DIM);
    }
}

// round 2
// speedup vs baseline: 2.8114x; 2.8114x over previous
#include <cuda_runtime.h>
#include <math.h>

// ---------------------------------------------------------------------------
// SelfAttention, B=4, S=2048, D=1024, fp32 in/out.
// Round 2: all GEMMs on tensor cores via mma.sync m16n8k8 TF32
// (cvt.rna.tf32.f32 for unbiased rounding). Double-buffered smem,
// conflict-free padded layouts.
// ---------------------------------------------------------------------------

#define BATCH 4
#define SEQ   2048
#define DIM   1024
#define ROWS  (BATCH * SEQ)          // 8192

#define BM 128
#define BN 128
#define BK 32

#define AS_STRIDE   36    // 32 + 4  -> frag addr 4m+k bijective over banks
#define BS_KN_STRIDE 136  // 128 + 8 -> frag addr 8k+n distinct
#define BS_NK_STRIDE 36

#define AS_SIZE 4608              // 128 * 36
#define BS_SIZE 4608              // max(128*36, 32*136=4352)
#define SMEM_BYTES (4 * (2 * AS_SIZE + 2 * BS_SIZE) / 1 ) // floats->bytes below
#define SMEM_TOTAL_BYTES ((2 * AS_SIZE + 2 * BS_SIZE) * 4) // 73728

// Scratch (allocation-free rule: device globals)
__device__ float g_Q[(size_t)ROWS * DIM];
__device__ float g_K[(size_t)ROWS * DIM];
__device__ float g_V[(size_t)ROWS * DIM];
__device__ float g_S[(size_t)BATCH * SEQ * SEQ];

__device__ __forceinline__ unsigned f2tf32(float f) {
    unsigned u;
    asm("cvt.rna.tf32.f32 %0, %1;" : "=r"(u) : "f"(f));
    return u;
}

__device__ __forceinline__ void mma_tf32(float* c, const unsigned* a, const unsigned* b) {
    asm volatile(
        "mma.sync.aligned.m16n8k8.row.col.f32.tf32.tf32.f32 "
        "{%0,%1,%2,%3}, {%4,%5,%6,%7}, {%8,%9}, {%0,%1,%2,%3};"
        : "+f"(c[0]), "+f"(c[1]), "+f"(c[2]), "+f"(c[3])
        : "r"(a[0]), "r"(a[1]), "r"(a[2]), "r"(a[3]), "r"(b[0]), "r"(b[1]));
}

// C[z] = alpha * A[z] @ op(B[z]) (+ bias)
//   TRANSB=false: B is [K,N] row-major (NN);  TRANSB=true: B is [N,K] (NT)
// M,N multiples of 128; K multiple of 32. 256 threads.
template <bool TRANSB, bool BIAS>
__global__ void __launch_bounds__(256)
tgemm(const float* __restrict__ A, const float* __restrict__ B,
      const float* __restrict__ bias, float* __restrict__ C,
      int M, int N, int K, float alpha, int sA, int sB, int sC)
{
    extern __shared__ unsigned smem_u[];
    unsigned* AsBase = smem_u;                 // [2][AS_SIZE]
    unsigned* BsBase = smem_u + 2 * AS_SIZE;   // [2][BS_SIZE]

    const int tid  = threadIdx.x;
    const int lane = tid & 31;
    const int warp = tid >> 5;
    const int wm   = warp >> 2;   // 0..1
    const int wn   = warp & 3;    // 0..3
    const int qr   = lane >> 2;   // 0..7
    const int qk   = lane & 3;    // 0..3
    const int bm   = blockIdx.y * BM;
    const int bn   = blockIdx.x * BN;

    A += (size_t)blockIdx.z * sA;
    B += (size_t)blockIdx.z * sB;
    C += (size_t)blockIdx.z * sC;

    const int ldb = TRANSB ? K : N;

    // global->reg load coordinates
    const int a_m = tid >> 3;          // 0..31, +32 per i
    const int a_k = (tid & 7) * 4;     // 0..28
    const int bkn_k = tid >> 5;        // 0..7, +8 per i (NN)
    const int bkn_n = (tid & 31) * 4;  // 0..124        (NN)

    float acc[4][4][4];
#pragma unroll
    for (int mt = 0; mt < 4; mt++)
#pragma unroll
        for (int nt = 0; nt < 4; nt++)
#pragma unroll
            for (int r = 0; r < 4; r++) acc[mt][nt][r] = 0.0f;

    float4 ra[4], rb[4];

    // ---- prologue: load k0 = 0, convert, store stage 0
#pragma unroll
    for (int i = 0; i < 4; i++)
        ra[i] = *(const float4*)(A + (size_t)(bm + a_m + 32 * i) * K + a_k);
    if (TRANSB) {
#pragma unroll
        for (int i = 0; i < 4; i++)
            rb[i] = *(const float4*)(B + (size_t)(bn + a_m + 32 * i) * ldb + a_k);
    } else {
#pragma unroll
        for (int i = 0; i < 4; i++)
            rb[i] = *(const float4*)(B + (size_t)(bkn_k + 8 * i) * ldb + bn + bkn_n);
    }
    {
        unsigned* As = AsBase;
        unsigned* Bs = BsBase;
#pragma unroll
        for (int i = 0; i < 4; i++) {
            unsigned* p = As + (a_m + 32 * i) * AS_STRIDE + a_k;
            p[0] = f2tf32(ra[i].x); p[1] = f2tf32(ra[i].y);
            p[2] = f2tf32(ra[i].z); p[3] = f2tf32(ra[i].w);
        }
        if (TRANSB) {
#pragma unroll
            for (int i = 0; i < 4; i++) {
                unsigned* p = Bs + (a_m + 32 * i) * BS_NK_STRIDE + a_k;
                p[0] = f2tf32(rb[i].x); p[1] = f2tf32(rb[i].y);
                p[2] = f2tf32(rb[i].z); p[3] = f2tf32(rb[i].w);
            }
        } else {
#pragma unroll
            for (int i = 0; i < 4; i++) {
                unsigned* p = Bs + (bkn_k + 8 * i) * BS_KN_STRIDE + bkn_n;
                p[0] = f2tf32(rb[i].x); p[1] = f2tf32(rb[i].y);
                p[2] = f2tf32(rb[i].z); p[3] = f2tf32(rb[i].w);
            }
        }
    }
    __syncthreads();

    int buf = 0;
    for (int k0 = BK; ; k0 += BK) {
        const bool more = (k0 < K);
        // ---- issue next-tile global loads early
        if (more) {
#pragma unroll
            for (int i = 0; i < 4; i++)
                ra[i] = *(const float4*)(A + (size_t)(bm + a_m + 32 * i) * K + k0 + a_k);
            if (TRANSB) {
#pragma unroll
                for (int i = 0; i < 4; i++)
                    rb[i] = *(const float4*)(B + (size_t)(bn + a_m + 32 * i) * ldb + k0 + a_k);
            } else {
#pragma unroll
                for (int i = 0; i < 4; i++)
                    rb[i] = *(const float4*)(B + (size_t)(k0 + bkn_k + 8 * i) * ldb + bn + bkn_n);
            }
        }

        // ---- compute on current stage
        {
            const unsigned* As = AsBase + buf * AS_SIZE;
            const unsigned* Bs = BsBase + buf * BS_SIZE;
#pragma unroll
            for (int ks = 0; ks < 4; ks++) {
                const int kf = ks * 8;
                unsigned af[4][4], bf[4][2];
#pragma unroll
                for (int mt = 0; mt < 4; mt++) {
                    int row = wm * 64 + mt * 16 + qr;
                    af[mt][0] = As[(row)     * AS_STRIDE + kf + qk];
                    af[mt][1] = As[(row + 8) * AS_STRIDE + kf + qk];
                    af[mt][2] = As[(row)     * AS_STRIDE + kf + qk + 4];
                    af[mt][3] = As[(row + 8) * AS_STRIDE + kf + qk + 4];
                }
#pragma unroll
                for (int nt = 0; nt < 4; nt++) {
                    int col = wn * 32 + nt * 8 + qr;
                    if (TRANSB) {
                        bf[nt][0] = Bs[col * BS_NK_STRIDE + kf + qk];
                        bf[nt][1] = Bs[col * BS_NK_STRIDE + kf + qk + 4];
                    } else {
                        bf[nt][0] = Bs[(kf + qk)     * BS_KN_STRIDE + col];
                        bf[nt][1] = Bs[(kf + qk + 4) * BS_KN_STRIDE + col];
                    }
                }
#pragma unroll
                for (int mt = 0; mt < 4; mt++)
#pragma unroll
                    for (int nt = 0; nt < 4; nt++)
                        mma_tf32(acc[mt][nt], af[mt], bf[nt]);
            }
        }

        if (!more) break;

        // ---- convert & store next tile into other stage
        {
            unsigned* As = AsBase + (buf ^ 1) * AS_SIZE;
            unsigned* Bs = BsBase + (buf ^ 1) * BS_SIZE;
#pragma unroll
            for (int i = 0; i < 4; i++) {
                unsigned* p = As + (a_m + 32 * i) * AS_STRIDE + a_k;
                p[0] = f2tf32(ra[i].x); p[1] = f2tf32(ra[i].y);
                p[2] = f2tf32(ra[i].z); p[3] = f2tf32(ra[i].w);
            }
            if (TRANSB) {
#pragma unroll
                for (int i = 0; i < 4; i++) {
                    unsigned* p = Bs + (a_m + 32 * i) * BS_NK_STRIDE + a_k;
                    p[0] = f2tf32(rb[i].x); p[1] = f2tf32(rb[i].y);
                    p[2] = f2tf32(rb[i].z); p[3] = f2tf32(rb[i].w);
                }
            } else {
#pragma unroll
                for (int i = 0; i < 4; i++) {
                    unsigned* p = Bs + (bkn_k + 8 * i) * BS_KN_STRIDE + bkn_n;
                    p[0] = f2tf32(rb[i].x); p[1] = f2tf32(rb[i].y);
                    p[2] = f2tf32(rb[i].z); p[3] = f2tf32(rb[i].w);
                }
            }
        }
        __syncthreads();
        buf ^= 1;
    }

    // ---- epilogue
#pragma unroll
    for (int mt = 0; mt < 4; mt++) {
        int r0 = bm + wm * 64 + mt * 16 + qr;
#pragma unroll
        for (int nt = 0; nt < 4; nt++) {
            int c = bn + wn * 32 + nt * 8 + qk * 2;
            float2 v0, v1;
            v0.x = acc[mt][nt][0] * alpha;
            v0.y = acc[mt][nt][1] * alpha;
            v1.x = acc[mt][nt][2] * alpha;
            v1.y = acc[mt][nt][3] * alpha;
            if (BIAS) {
                float b0 = bias[c], b1 = bias[c + 1];
                v0.x += b0; v0.y += b1;
                v1.x += b0; v1.y += b1;
            }
            *(float2*)(C + (size_t)r0 * N + c)       = v0;
            *(float2*)(C + (size_t)(r0 + 8) * N + c) = v1;
        }
    }
}

// In-place row softmax over rows of length 2048. One block (256 thr) per row.
__global__ void __launch_bounds__(256)
softmax2048(float* __restrict__ S)
{
    __shared__ float red_max[8];
    __shared__ float red_sum[8];

    float* p = S + (size_t)blockIdx.x * 2048;
    const int t = threadIdx.x;

    float4 v0 = ((const float4*)p)[t];
    float4 v1 = ((const float4*)p)[t + 256];

    float m = fmaxf(fmaxf(fmaxf(v0.x, v0.y), fmaxf(v0.z, v0.w)),
                    fmaxf(fmaxf(v1.x, v1.y), fmaxf(v1.z, v1.w)));
#pragma unroll
    for (int o = 16; o; o >>= 1)
        m = fmaxf(m, __shfl_xor_sync(0xffffffffu, m, o));
    if ((t & 31) == 0) red_max[t >> 5] = m;
    __syncthreads();
    m = red_max[0];
#pragma unroll
    for (int w = 1; w < 8; w++) m = fmaxf(m, red_max[w]);

    v0.x = expf(v0.x - m); v0.y = expf(v0.y - m);
    v0.z = expf(v0.z - m); v0.w = expf(v0.w - m);
    v1.x = expf(v1.x - m); v1.y = expf(v1.y - m);
    v1.z = expf(v1.z - m); v1.w = expf(v1.w - m);

    float s = (v0.x + v0.y + v0.z + v0.w) + (v1.x + v1.y + v1.z + v1.w);
#pragma unroll
    for (int o = 16; o; o >>= 1)
        s += __shfl_xor_sync(0xffffffffu, s, o);
    if ((t & 31) == 0) red_sum[t >> 5] = s;
    __syncthreads();
    s = red_sum[0];
#pragma unroll
    for (int w = 1; w < 8; w++) s += red_sum[w];

    float inv = 1.0f / s;
    v0.x *= inv; v0.y *= inv; v0.z *= inv; v0.w *= inv;
    v1.x *= inv; v1.y *= inv; v1.z *= inv; v1.w *= inv;

    ((float4*)p)[t]       = v0;
    ((float4*)p)[t + 256] = v1;
}

extern "C" void kernel_launch(void* const* d_in, const int* in_sizes, int n_in,
                              void* d_out, int out_size)
{
    (void)in_sizes; (void)n_in; (void)out_size;
    const float* x  = (const float*)d_in[0];
    const float* Wq = (const float*)d_in[1];
    const float* bq = (const float*)d_in[2];
    const float* Wk = (const float*)d_in[3];
    const float* bk = (const float*)d_in[4];
    const float* Wv = (const float*)d_in[5];
    const float* bv = (const float*)d_in[6];
    float* out = (float*)d_out;

    float *Q, *K, *V, *S;
    cudaGetSymbolAddress((void**)&Q, g_Q);
    cudaGetSymbolAddress((void**)&K, g_K);
    cudaGetSymbolAddress((void**)&V, g_V);
    cudaGetSymbolAddress((void**)&S, g_S);

    static bool attr_done = false;
    if (!attr_done) {
        cudaFuncSetAttribute(tgemm<false, true>,
                             cudaFuncAttributeMaxDynamicSharedMemorySize, SMEM_TOTAL_BYTES);
        cudaFuncSetAttribute(tgemm<true, false>,
                             cudaFuncAttributeMaxDynamicSharedMemorySize, SMEM_TOTAL_BYTES);
        cudaFuncSetAttribute(tgemm<false, false>,
                             cudaFuncAttributeMaxDynamicSharedMemorySize, SMEM_TOTAL_BYTES);
        attr_done = true;
    }

    const float inv_sqrt_d = 0.03125f;  // 1/sqrt(1024)

    // 1) QKV projections: [8192,1024] x [1024,1024] (+bias)
    {
        dim3 grid(DIM / BN, ROWS / BM, 1);
        tgemm<false, true><<<grid, 256, SMEM_TOTAL_BYTES>>>(x, Wq, bq, Q, ROWS, DIM, DIM, 1.0f, 0, 0, 0);
        tgemm<false, true><<<grid, 256, SMEM_TOTAL_BYTES>>>(x, Wk, bk, K, ROWS, DIM, DIM, 1.0f, 0, 0, 0);
        tgemm<false, true><<<grid, 256, SMEM_TOTAL_BYTES>>>(x, Wv, bv, V, ROWS, DIM, DIM, 1.0f, 0, 0, 0);
    }

    // 2) scores = Q @ K^T * (1/sqrt(D)), batched over 4
    {
        dim3 grid(SEQ / BN, SEQ / BM, BATCH);
        tgemm<true, false><<<grid, 256, SMEM_TOTAL_BYTES>>>(Q, K, nullptr, S,
                                                            SEQ, SEQ, DIM, inv_sqrt_d,
                                                            SEQ * DIM, SEQ * DIM, SEQ * SEQ);
    }

    // 3) softmax rows
    softmax2048<<<BATCH * SEQ, 256>>>(S);

    // 4) out = P @ V, batched over 4
    {
        dim3 grid(DIM / BN, SEQ / BM, BATCH);
        tgemm<false, false><<<grid, 256, SMEM_TOTAL_BYTES>>>(S, V, nullptr, out,
                                                             SEQ, DIM, SEQ, 1.0f,
                                                             SEQ * SEQ, SEQ * DIM, SEQ * DIM);
    }
}

// round 4
// speedup vs baseline: 3.0838x; 1.0969x over previous
#include <cuda_runtime.h>
#include <cstdint>
#include <math.h>

// ---------------------------------------------------------------------------
// SelfAttention, B=4, S=2048, D=1024, fp32 in/out.
// Round 4: mma.sync tf32 (tcgen05 unavailable: harness PTX target is sm_103).
// All operands pre-rounded to tf32 in gmem -> GEMM inner loop has no cvt;
// cp.async.cg 4-stage pipeline global->smem.
// ---------------------------------------------------------------------------

#define BATCH 4
#define SEQ   2048
#define DIM   1024
#define ROWS  (BATCH * SEQ)          // 8192

#define BM 128
#define BN 128
#define BK 32
#define NSTAGES 4

#define AS_STRIDE    36    // 32 + 4
#define BS_KN_STRIDE 136   // 128 + 8
#define BS_NK_STRIDE 36
#define AS_SIZE 4608               // 128 * 36
#define BS_SIZE 4608               // max(128*36, 32*136)
#define STAGE_SIZE (AS_SIZE + BS_SIZE)              // floats per stage
#define SMEM_TOTAL_BYTES (NSTAGES * STAGE_SIZE * 4) // 147456

// Scratch (allocation-free rule: device globals)
__device__ float g_xr [(size_t)ROWS * DIM];
__device__ float g_Wqr[(size_t)DIM * DIM];
__device__ float g_Wkr[(size_t)DIM * DIM];
__device__ float g_Wvr[(size_t)DIM * DIM];
__device__ float g_Q  [(size_t)ROWS * DIM];
__device__ float g_K  [(size_t)ROWS * DIM];
__device__ float g_V  [(size_t)ROWS * DIM];
__device__ float g_S  [(size_t)BATCH * SEQ * SEQ];

__device__ __forceinline__ uint32_t smem_u32(const void* p) {
    uint32_t a;
    asm("{ .reg .u64 t; cvta.to.shared.u64 t, %1; cvt.u32.u64 %0, t; }" : "=r"(a) : "l"(p));
    return a;
}
__device__ __forceinline__ float round_tf32(float f) {
    uint32_t u;
    asm("cvt.rna.tf32.f32 %0, %1;" : "=r"(u) : "f"(f));
    return __uint_as_float(u);
}
__device__ __forceinline__ void cp_async16(uint32_t dst, const void* src) {
    asm volatile("cp.async.cg.shared.global [%0], [%1], 16;" :: "r"(dst), "l"(src));
}
__device__ __forceinline__ void mma_tf32(float* c, const unsigned* a, const unsigned* b) {
    asm volatile(
        "mma.sync.aligned.m16n8k8.row.col.f32.tf32.tf32.f32 "
        "{%0,%1,%2,%3}, {%4,%5,%6,%7}, {%8,%9}, {%0,%1,%2,%3};"
        : "+f"(c[0]), "+f"(c[1]), "+f"(c[2]), "+f"(c[3])
        : "r"(a[0]), "r"(a[1]), "r"(a[2]), "r"(a[3]), "r"(b[0]), "r"(b[1]));
}

// C[z] = alpha * A[z] @ op(B[z]) (+ bias[n]) ; operands must be tf32-valued fp32.
//   TRANSB=false: B is [K,N] row-major (NN);  TRANSB=true: B is [N,K] (NT)
// M,N multiples of 128; K multiple of 32, K/32 >= NSTAGES-1. 256 threads.
template <bool TRANSB, bool BIAS, bool ROUND_OUT>
__global__ void __launch_bounds__(256)
tgemm(const float* __restrict__ A, const float* __restrict__ B,
      const float* __restrict__ bias, float* __restrict__ C,
      int M, int N, int K, float alpha, int sA, int sB, int sC)
{
    extern __shared__ float smemf[];
    const uint32_t sb = smem_u32(smemf);

    const int tid  = threadIdx.x;
    const int lane = tid & 31;
    const int warp = tid >> 5;
    const int wm   = warp >> 2;   // 0..1
    const int wn   = warp & 3;    // 0..3
    const int qr   = lane >> 2;   // 0..7
    const int qk   = lane & 3;    // 0..3
    const int bm   = blockIdx.y * BM;
    const int bn   = blockIdx.x * BN;

    A += (size_t)blockIdx.z * sA;
    B += (size_t)blockIdx.z * sB;
    C += (size_t)blockIdx.z * sC;

    // global->smem load coordinates
    const int a_m   = tid >> 3;          // 0..31, +32 per i
    const int a_k   = (tid & 7) * 4;     // 0..28
    const int bkn_k = tid >> 5;          // 0..7, +8 per i (NN)
    const int bkn_n = (tid & 31) * 4;    // 0..124        (NN)

    const int T = K / BK;

    auto issue_tile = [&](int t) {
        const int slot = t % NSTAGES;
        const uint32_t as = sb + (uint32_t)(slot * STAGE_SIZE) * 4;
        const uint32_t bs = as + AS_SIZE * 4;
        const int k0 = t * BK;
#pragma unroll
        for (int i = 0; i < 4; i++) {
            int m = a_m + 32 * i;
            cp_async16(as + (uint32_t)(m * AS_STRIDE + a_k) * 4,
                       A + (size_t)(bm + m) * K + k0 + a_k);
        }
        if (TRANSB) {
#pragma unroll
            for (int i = 0; i < 4; i++) {
                int n = a_m + 32 * i;
                cp_async16(bs + (uint32_t)(n * BS_NK_STRIDE + a_k) * 4,
                           B + (size_t)(bn + n) * K + k0 + a_k);
            }
        } else {
#pragma unroll
            for (int i = 0; i < 4; i++) {
                int kk = bkn_k + 8 * i;
                cp_async16(bs + (uint32_t)(kk * BS_KN_STRIDE + bkn_n) * 4,
                           B + (size_t)(k0 + kk) * N + bn + bkn_n);
            }
        }
        asm volatile("cp.async.commit_group;" ::: "memory");
    };

    float acc[4][4][4];
#pragma unroll
    for (int mt = 0; mt < 4; mt++)
#pragma unroll
        for (int nt = 0; nt < 4; nt++)
#pragma unroll
            for (int r = 0; r < 4; r++) acc[mt][nt][r] = 0.0f;

    // prologue: fill NSTAGES-1 stages
    issue_tile(0); issue_tile(1); issue_tile(2);

    for (int i = 0; i < T; i++) {
        asm volatile("cp.async.wait_group 2;" ::: "memory");
        __syncthreads();

        if (i + 3 < T) issue_tile(i + 3);
        else asm volatile("cp.async.commit_group;" ::: "memory");

        const int slot = i % NSTAGES;
        const unsigned* As = (const unsigned*)smemf + slot * STAGE_SIZE;
        const unsigned* Bs = As + AS_SIZE;
#pragma unroll
        for (int ks = 0; ks < 4; ks++) {
            const int kf = ks * 8;
            unsigned af[4][4], bf[4][2];
#pragma unroll
            for (int mt = 0; mt < 4; mt++) {
                int row = wm * 64 + mt * 16 + qr;
                af[mt][0] = As[(row)     * AS_STRIDE + kf + qk];
                af[mt][1] = As[(row + 8) * AS_STRIDE + kf + qk];
                af[mt][2] = As[(row)     * AS_STRIDE + kf + qk + 4];
                af[mt][3] = As[(row + 8) * AS_STRIDE + kf + qk + 4];
            }
#pragma unroll
            for (int nt = 0; nt < 4; nt++) {
                int col = wn * 32 + nt * 8 + qr;
                if (TRANSB) {
                    bf[nt][0] = Bs[col * BS_NK_STRIDE + kf + qk];
                    bf[nt][1] = Bs[col * BS_NK_STRIDE + kf + qk + 4];
                } else {
                    bf[nt][0] = Bs[(kf + qk)     * BS_KN_STRIDE + col];
                    bf[nt][1] = Bs[(kf + qk + 4) * BS_KN_STRIDE + col];
                }
            }
#pragma unroll
            for (int mt = 0; mt < 4; mt++)
#pragma unroll
                for (int nt = 0; nt < 4; nt++)
                    mma_tf32(acc[mt][nt], af[mt], bf[nt]);
        }
    }

    // ---- epilogue
#pragma unroll
    for (int mt = 0; mt < 4; mt++) {
        int r0 = bm + wm * 64 + mt * 16 + qr;
#pragma unroll
        for (int nt = 0; nt < 4; nt++) {
            int c = bn + wn * 32 + nt * 8 + qk * 2;
            float2 v0, v1;
            v0.x = acc[mt][nt][0] * alpha;
            v0.y = acc[mt][nt][1] * alpha;
            v1.x = acc[mt][nt][2] * alpha;
            v1.y = acc[mt][nt][3] * alpha;
            if (BIAS) {
                float b0 = bias[c], b1 = bias[c + 1];
                v0.x += b0; v0.y += b1;
                v1.x += b0; v1.y += b1;
            }
            if (ROUND_OUT) {
                v0.x = round_tf32(v0.x); v0.y = round_tf32(v0.y);
                v1.x = round_tf32(v1.x); v1.y = round_tf32(v1.y);
            }
            *(float2*)(C + (size_t)r0 * N + c)       = v0;
            *(float2*)(C + (size_t)(r0 + 8) * N + c) = v1;
        }
    }
}

// tf32-round copy
__global__ void __launch_bounds__(256)
round_copy4(const float4* __restrict__ in, float4* __restrict__ out, int n4)
{
    int i = blockIdx.x * 256 + threadIdx.x;
    if (i < n4) {
        float4 v = in[i];
        v.x = round_tf32(v.x); v.y = round_tf32(v.y);
        v.z = round_tf32(v.z); v.w = round_tf32(v.w);
        out[i] = v;
    }
}

// In-place softmax over rows of 2048; output rounded to tf32 (it is an MMA operand).
__global__ void __launch_bounds__(256)
softmax2048(float* __restrict__ S)
{
    __shared__ float red_max[8];
    __shared__ float red_sum[8];
    float* p = S + (size_t)blockIdx.x * 2048;
    const int t = threadIdx.x;

    float4 v0 = ((const float4*)p)[t];
    float4 v1 = ((const float4*)p)[t + 256];

    float m = fmaxf(fmaxf(fmaxf(v0.x, v0.y), fmaxf(v0.z, v0.w)),
                    fmaxf(fmaxf(v1.x, v1.y), fmaxf(v1.z, v1.w)));
#pragma unroll
    for (int o = 16; o; o >>= 1) m = fmaxf(m, __shfl_xor_sync(0xffffffffu, m, o));
    if ((t & 31) == 0) red_max[t >> 5] = m;
    __syncthreads();
    m = red_max[0];
#pragma unroll
    for (int w = 1; w < 8; w++) m = fmaxf(m, red_max[w]);

    v0.x = expf(v0.x - m); v0.y = expf(v0.y - m);
    v0.z = expf(v0.z - m); v0.w = expf(v0.w - m);
    v1.x = expf(v1.x - m); v1.y = expf(v1.y - m);
    v1.z = expf(v1.z - m); v1.w = expf(v1.w - m);

    float s = (v0.x + v0.y + v0.z + v0.w) + (v1.x + v1.y + v1.z + v1.w);
#pragma unroll
    for (int o = 16; o; o >>= 1) s += __shfl_xor_sync(0xffffffffu, s, o);
    if ((t & 31) == 0) red_sum[t >> 5] = s;
    __syncthreads();
    s = red_sum[0];
#pragma unroll
    for (int w = 1; w < 8; w++) s += red_sum[w];

    float inv = 1.0f / s;
    v0.x = round_tf32(v0.x * inv); v0.y = round_tf32(v0.y * inv);
    v0.z = round_tf32(v0.z * inv); v0.w = round_tf32(v0.w * inv);
    v1.x = round_tf32(v1.x * inv); v1.y = round_tf32(v1.y * inv);
    v1.z = round_tf32(v1.z * inv); v1.w = round_tf32(v1.w * inv);

    ((float4*)p)[t]       = v0;
    ((float4*)p)[t + 256] = v1;
}

extern "C" void kernel_launch(void* const* d_in, const int* in_sizes, int n_in,
                              void* d_out, int out_size)
{
    (void)in_sizes; (void)n_in; (void)out_size;
    const float* x  = (const float*)d_in[0];
    const float* Wq = (const float*)d_in[1];
    const float* bq = (const float*)d_in[2];
    const float* Wk = (const float*)d_in[3];
    const float* bk = (const float*)d_in[4];
    const float* Wv = (const float*)d_in[5];
    const float* bv = (const float*)d_in[6];
    float* out = (float*)d_out;

    float *xr, *Wqr, *Wkr, *Wvr, *Q, *K, *V, *S;
    cudaGetSymbolAddress((void**)&xr,  g_xr);
    cudaGetSymbolAddress((void**)&Wqr, g_Wqr);
    cudaGetSymbolAddress((void**)&Wkr, g_Wkr);
    cudaGetSymbolAddress((void**)&Wvr, g_Wvr);
    cudaGetSymbolAddress((void**)&Q,   g_Q);
    cudaGetSymbolAddress((void**)&K,   g_K);
    cudaGetSymbolAddress((void**)&V,   g_V);
    cudaGetSymbolAddress((void**)&S,   g_S);

    cudaFuncSetAttribute(tgemm<false, true,  true >,
                         cudaFuncAttributeMaxDynamicSharedMemorySize, SMEM_TOTAL_BYTES);
    cudaFuncSetAttribute(tgemm<true,  false, false>,
                         cudaFuncAttributeMaxDynamicSharedMemorySize, SMEM_TOTAL_BYTES);
    cudaFuncSetAttribute(tgemm<false, false, false>,
                         cudaFuncAttributeMaxDynamicSharedMemorySize, SMEM_TOTAL_BYTES);

    const float inv_sqrt_d = 0.03125f;  // 1/sqrt(1024)

    // 0) pre-round operands to tf32
    round_copy4<<<(ROWS * DIM / 4 + 255) / 256, 256>>>((const float4*)x, (float4*)xr, ROWS * DIM / 4);
    round_copy4<<<(DIM * DIM / 4 + 255) / 256, 256>>>((const float4*)Wq, (float4*)Wqr, DIM * DIM / 4);
    round_copy4<<<(DIM * DIM / 4 + 255) / 256, 256>>>((const float4*)Wk, (float4*)Wkr, DIM * DIM / 4);
    round_copy4<<<(DIM * DIM / 4 + 255) / 256, 256>>>((const float4*)Wv, (float4*)Wvr, DIM * DIM / 4);

    // 1) QKV projections (outputs rounded to tf32: they are MMA operands next)
    {
        dim3 g(DIM / BN, ROWS / BM, 1);
        tgemm<false, true, true><<<g, 256, SMEM_TOTAL_BYTES>>>(xr, Wqr, bq, Q, ROWS, DIM, DIM, 1.0f, 0, 0, 0);
        tgemm<false, true, true><<<g, 256, SMEM_TOTAL_BYTES>>>(xr, Wkr, bk, K, ROWS, DIM, DIM, 1.0f, 0, 0, 0);
        tgemm<false, true, true><<<g, 256, SMEM_TOTAL_BYTES>>>(xr, Wvr, bv, V, ROWS, DIM, DIM, 1.0f, 0, 0, 0);
    }

    // 2) scores = Q @ K^T / 32
    {
        dim3 g(SEQ / BN, SEQ / BM, BATCH);
        tgemm<true, false, false><<<g, 256, SMEM_TOTAL_BYTES>>>(Q, K, nullptr, S,
                                                                SEQ, SEQ, DIM, inv_sqrt_d,
                                                                SEQ * DIM, SEQ * DIM, SEQ * SEQ);
    }

    // 3) softmax (rounds P to tf32)
    softmax2048<<<BATCH * SEQ, 256>>>(S);

    // 4) out = P @ V
    {
        dim3 g(DIM / BN, SEQ / BM, BATCH);
        tgemm<false, false, false><<<g, 256, SMEM_TOTAL_BYTES>>>(S, V, nullptr, out,
                                                                 SEQ, DIM, SEQ, 1.0f,
                                                                 SEQ * SEQ, SEQ * DIM, SEQ * DIM);
    }
}

// round 5
// speedup vs baseline: 3.3196x; 1.0765x over previous
#include <cuda_runtime.h>
#include <cstdint>
#include <math.h>

// ---------------------------------------------------------------------------
// SelfAttention, B=4, S=2048, D=1024, fp32 in/out.
// Round 5: mma.sync tf32; 128-thread CTAs (BM=64,BN=128,BK=32), 2 CTAs/SM
// so barriers/waits of one CTA are hidden by the other. Operands pre-rounded
// to tf32 in gmem; cp.async.cg 4-stage pipeline.
// ---------------------------------------------------------------------------

#define BATCH 4
#define SEQ   2048
#define DIM   1024
#define ROWS  (BATCH * SEQ)          // 8192

#define BM 64
#define BN 128
#define BK 32
#define NSTAGES 4

#define AS_STRIDE    36    // 32 + 4
#define BS_KN_STRIDE 136   // 128 + 8
#define BS_NK_STRIDE 36
#define AS_SIZE 2304               // 64 * 36
#define BS_SIZE 4608               // max(128*36, 32*136)
#define STAGE_SIZE (AS_SIZE + BS_SIZE)              // 6912 floats
#define SMEM_TOTAL_BYTES (NSTAGES * STAGE_SIZE * 4) // 110592

// Scratch (allocation-free rule: device globals)
__device__ float g_xr [(size_t)ROWS * DIM];
__device__ float g_Wqr[(size_t)DIM * DIM];
__device__ float g_Wkr[(size_t)DIM * DIM];
__device__ float g_Wvr[(size_t)DIM * DIM];
__device__ float g_Q  [(size_t)ROWS * DIM];
__device__ float g_K  [(size_t)ROWS * DIM];
__device__ float g_V  [(size_t)ROWS * DIM];
__device__ float g_S  [(size_t)BATCH * SEQ * SEQ];

__device__ __forceinline__ uint32_t smem_u32(const void* p) {
    uint32_t a;
    asm("{ .reg .u64 t; cvta.to.shared.u64 t, %1; cvt.u32.u64 %0, t; }" : "=r"(a) : "l"(p));
    return a;
}
__device__ __forceinline__ float round_tf32(float f) {
    uint32_t u;
    asm("cvt.rna.tf32.f32 %0, %1;" : "=r"(u) : "f"(f));
    return __uint_as_float(u);
}
__device__ __forceinline__ void cp_async16(uint32_t dst, const void* src) {
    asm volatile("cp.async.cg.shared.global [%0], [%1], 16;" :: "r"(dst), "l"(src));
}
__device__ __forceinline__ void mma_tf32(float* c, const unsigned* a, const unsigned* b) {
    asm volatile(
        "mma.sync.aligned.m16n8k8.row.col.f32.tf32.tf32.f32 "
        "{%0,%1,%2,%3}, {%4,%5,%6,%7}, {%8,%9}, {%0,%1,%2,%3};"
        : "+f"(c[0]), "+f"(c[1]), "+f"(c[2]), "+f"(c[3])
        : "r"(a[0]), "r"(a[1]), "r"(a[2]), "r"(a[3]), "r"(b[0]), "r"(b[1]));
}

// C[z] = alpha * A[z] @ op(B[z]) (+ bias[n]) ; operands must be tf32-valued fp32.
//   TRANSB=false: B is [K,N] row-major (NN);  TRANSB=true: B is [N,K] (NT)
// M mult of 64, N mult of 128, K mult of 32 with K/32 >= 3. 128 threads, 2 CTAs/SM.
template <bool TRANSB, bool BIAS, bool ROUND_OUT>
__global__ void __launch_bounds__(128, 2)
tgemm(const float* __restrict__ A, const float* __restrict__ B,
      const float* __restrict__ bias, float* __restrict__ C,
      int M, int N, int K, float alpha, int sA, int sB, int sC)
{
    extern __shared__ float smemf[];
    const uint32_t sb = smem_u32(smemf);

    const int tid  = threadIdx.x;
    const int lane = tid & 31;
    const int wn   = tid >> 5;    // warp 0..3 -> 32-col slice
    const int qr   = lane >> 2;   // 0..7
    const int qk   = lane & 3;    // 0..3
    const int bm   = blockIdx.y * BM;
    const int bn   = blockIdx.x * BN;

    A += (size_t)blockIdx.z * sA;
    B += (size_t)blockIdx.z * sB;
    C += (size_t)blockIdx.z * sC;

    // global->smem coords (128 threads)
    const int a_m   = tid >> 3;          // 0..15, +16 per i (4 iters -> 64 rows)
    const int a_k   = (tid & 7) * 4;     // 0..28
    const int bnt_n = tid >> 3;          // 0..15, +16 per i (8 iters -> 128 rows, NT)
    const int bkn_k = tid >> 5;          // 0..3,  +4 per i (8 iters -> 32 rows, NN)
    const int bkn_n = (tid & 31) * 4;    // 0..124

    const int T = K / BK;

    auto issue_tile = [&](int t) {
        const int slot = t % NSTAGES;
        const uint32_t as = sb + (uint32_t)(slot * STAGE_SIZE) * 4;
        const uint32_t bs = as + AS_SIZE * 4;
        const int k0 = t * BK;
#pragma unroll
        for (int i = 0; i < 4; i++) {
            int m = a_m + 16 * i;
            cp_async16(as + (uint32_t)(m * AS_STRIDE + a_k) * 4,
                       A + (size_t)(bm + m) * K + k0 + a_k);
        }
        if (TRANSB) {
#pragma unroll
            for (int i = 0; i < 8; i++) {
                int n = bnt_n + 16 * i;
                cp_async16(bs + (uint32_t)(n * BS_NK_STRIDE + a_k) * 4,
                           B + (size_t)(bn + n) * K + k0 + a_k);
            }
        } else {
#pragma unroll
            for (int i = 0; i < 8; i++) {
                int kk = bkn_k + 4 * i;
                cp_async16(bs + (uint32_t)(kk * BS_KN_STRIDE + bkn_n) * 4,
                           B + (size_t)(k0 + kk) * N + bn + bkn_n);
            }
        }
        asm volatile("cp.async.commit_group;" ::: "memory");
    };

    float acc[4][4][4];
#pragma unroll
    for (int mt = 0; mt < 4; mt++)
#pragma unroll
        for (int nt = 0; nt < 4; nt++)
#pragma unroll
            for (int r = 0; r < 4; r++) acc[mt][nt][r] = 0.0f;

    issue_tile(0); issue_tile(1); issue_tile(2);

    for (int i = 0; i < T; i++) {
        asm volatile("cp.async.wait_group 2;" ::: "memory");
        __syncthreads();

        if (i + 3 < T) issue_tile(i + 3);
        else asm volatile("cp.async.commit_group;" ::: "memory");

        const int slot = i % NSTAGES;
        const unsigned* As = (const unsigned*)smemf + slot * STAGE_SIZE;
        const unsigned* Bs = As + AS_SIZE;
#pragma unroll
        for (int ks = 0; ks < 4; ks++) {
            const int kf = ks * 8;
            unsigned af[4][4], bf[4][2];
#pragma unroll
            for (int mt = 0; mt < 4; mt++) {
                int row = mt * 16 + qr;
                af[mt][0] = As[(row)     * AS_STRIDE + kf + qk];
                af[mt][1] = As[(row + 8) * AS_STRIDE + kf + qk];
                af[mt][2] = As[(row)     * AS_STRIDE + kf + qk + 4];
                af[mt][3] = As[(row + 8) * AS_STRIDE + kf + qk + 4];
            }
#pragma unroll
            for (int nt = 0; nt < 4; nt++) {
                int col = wn * 32 + nt * 8 + qr;
                if (TRANSB) {
                    bf[nt][0] = Bs[col * BS_NK_STRIDE + kf + qk];
                    bf[nt][1] = Bs[col * BS_NK_STRIDE + kf + qk + 4];
                } else {
                    bf[nt][0] = Bs[(kf + qk)     * BS_KN_STRIDE + col];
                    bf[nt][1] = Bs[(kf + qk + 4) * BS_KN_STRIDE + col];
                }
            }
#pragma unroll
            for (int mt = 0; mt < 4; mt++)
#pragma unroll
                for (int nt = 0; nt < 4; nt++)
                    mma_tf32(acc[mt][nt], af[mt], bf[nt]);
        }
    }

    // ---- epilogue
#pragma unroll
    for (int mt = 0; mt < 4; mt++) {
        int r0 = bm + mt * 16 + qr;
#pragma unroll
        for (int nt = 0; nt < 4; nt++) {
            int c = bn + wn * 32 + nt * 8 + qk * 2;
            float2 v0, v1;
            v0.x = acc[mt][nt][0] * alpha;
            v0.y = acc[mt][nt][1] * alpha;
            v1.x = acc[mt][nt][2] * alpha;
            v1.y = acc[mt][nt][3] * alpha;
            if (BIAS) {
                float b0 = bias[c], b1 = bias[c + 1];
                v0.x += b0; v0.y += b1;
                v1.x += b0; v1.y += b1;
            }
            if (ROUND_OUT) {
                v0.x = round_tf32(v0.x); v0.y = round_tf32(v0.y);
                v1.x = round_tf32(v1.x); v1.y = round_tf32(v1.y);
            }
            *(float2*)(C + (size_t)r0 * N + c)       = v0;
            *(float2*)(C + (size_t)(r0 + 8) * N + c) = v1;
        }
    }
}

// tf32-round copy
__global__ void __launch_bounds__(256)
round_copy4(const float4* __restrict__ in, float4* __restrict__ out, int n4)
{
    int i = blockIdx.x * 256 + threadIdx.x;
    if (i < n4) {
        float4 v = in[i];
        v.x = round_tf32(v.x); v.y = round_tf32(v.y);
        v.z = round_tf32(v.z); v.w = round_tf32(v.w);
        out[i] = v;
    }
}

// In-place softmax over rows of 2048; output rounded to tf32 (it is an MMA operand).
__global__ void __launch_bounds__(256)
softmax2048(float* __restrict__ S)
{
    __shared__ float red_max[8];
    __shared__ float red_sum[8];
    float* p = S + (size_t)blockIdx.x * 2048;
    const int t = threadIdx.x;

    float4 v0 = ((const float4*)p)[t];
    float4 v1 = ((const float4*)p)[t + 256];

    float m = fmaxf(fmaxf(fmaxf(v0.x, v0.y), fmaxf(v0.z, v0.w)),
                    fmaxf(fmaxf(v1.x, v1.y), fmaxf(v1.z, v1.w)));
#pragma unroll
    for (int o = 16; o; o >>= 1) m = fmaxf(m, __shfl_xor_sync(0xffffffffu, m, o));
    if ((t & 31) == 0) red_max[t >> 5] = m;
    __syncthreads();
    m = red_max[0];
#pragma unroll
    for (int w = 1; w < 8; w++) m = fmaxf(m, red_max[w]);

    v0.x = expf(v0.x - m); v0.y = expf(v0.y - m);
    v0.z = expf(v0.z - m); v0.w = expf(v0.w - m);
    v1.x = expf(v1.x - m); v1.y = expf(v1.y - m);
    v1.z = expf(v1.z - m); v1.w = expf(v1.w - m);

    float s = (v0.x + v0.y + v0.z + v0.w) + (v1.x + v1.y + v1.z + v1.w);
#pragma unroll
    for (int o = 16; o; o >>= 1) s += __shfl_xor_sync(0xffffffffu, s, o);
    if ((t & 31) == 0) red_sum[t >> 5] = s;
    __syncthreads();
    s = red_sum[0];
#pragma unroll
    for (int w = 1; w < 8; w++) s += red_sum[w];

    float inv = 1.0f / s;
    v0.x = round_tf32(v0.x * inv); v0.y = round_tf32(v0.y * inv);
    v0.z = round_tf32(v0.z * inv); v0.w = round_tf32(v0.w * inv);
    v1.x = round_tf32(v1.x * inv); v1.y = round_tf32(v1.y * inv);
    v1.z = round_tf32(v1.z * inv); v1.w = round_tf32(v1.w * inv);

    ((float4*)p)[t]       = v0;
    ((float4*)p)[t + 256] = v1;
}

extern "C" void kernel_launch(void* const* d_in, const int* in_sizes, int n_in,
                              void* d_out, int out_size)
{
    (void)in_sizes; (void)n_in; (void)out_size;
    const float* x  = (const float*)d_in[0];
    const float* Wq = (const float*)d_in[1];
    const float* bq = (const float*)d_in[2];
    const float* Wk = (const float*)d_in[3];
    const float* bk = (const float*)d_in[4];
    const float* Wv = (const float*)d_in[5];
    const float* bv = (const float*)d_in[6];
    float* out = (float*)d_out;

    float *xr, *Wqr, *Wkr, *Wvr, *Q, *K, *V, *S;
    cudaGetSymbolAddress((void**)&xr,  g_xr);
    cudaGetSymbolAddress((void**)&Wqr, g_Wqr);
    cudaGetSymbolAddress((void**)&Wkr, g_Wkr);
    cudaGetSymbolAddress((void**)&Wvr, g_Wvr);
    cudaGetSymbolAddress((void**)&Q,   g_Q);
    cudaGetSymbolAddress((void**)&K,   g_K);
    cudaGetSymbolAddress((void**)&V,   g_V);
    cudaGetSymbolAddress((void**)&S,   g_S);

    cudaFuncSetAttribute(tgemm<false, true,  true >,
                         cudaFuncAttributeMaxDynamicSharedMemorySize, SMEM_TOTAL_BYTES);
    cudaFuncSetAttribute(tgemm<true,  false, false>,
                         cudaFuncAttributeMaxDynamicSharedMemorySize, SMEM_TOTAL_BYTES);
    cudaFuncSetAttribute(tgemm<false, false, false>,
                         cudaFuncAttributeMaxDynamicSharedMemorySize, SMEM_TOTAL_BYTES);

    const float inv_sqrt_d = 0.03125f;  // 1/sqrt(1024)

    // 0) pre-round operands to tf32
    round_copy4<<<(ROWS * DIM / 4 + 255) / 256, 256>>>((const float4*)x, (float4*)xr, ROWS * DIM / 4);
    round_copy4<<<(DIM * DIM / 4 + 255) / 256, 256>>>((const float4*)Wq, (float4*)Wqr, DIM * DIM / 4);
    round_copy4<<<(DIM * DIM / 4 + 255) / 256, 256>>>((const float4*)Wk, (float4*)Wkr, DIM * DIM / 4);
    round_copy4<<<(DIM * DIM / 4 + 255) / 256, 256>>>((const float4*)Wv, (float4*)Wvr, DIM * DIM / 4);

    // 1) QKV projections (outputs rounded to tf32: they are MMA operands next)
    {
        dim3 g(DIM / BN, ROWS / BM, 1);
        tgemm<false, true, true><<<g, 128, SMEM_TOTAL_BYTES>>>(xr, Wqr, bq, Q, ROWS, DIM, DIM, 1.0f, 0, 0, 0);
        tgemm<false, true, true><<<g, 128, SMEM_TOTAL_BYTES>>>(xr, Wkr, bk, K, ROWS, DIM, DIM, 1.0f, 0, 0, 0);
        tgemm<false, true, true><<<g, 128, SMEM_TOTAL_BYTES>>>(xr, Wvr, bv, V, ROWS, DIM, DIM, 1.0f, 0, 0, 0);
    }

    // 2) scores = Q @ K^T / 32
    {
        dim3 g(SEQ / BN, SEQ / BM, BATCH);
        tgemm<true, false, false><<<g, 128, SMEM_TOTAL_BYTES>>>(Q, K, nullptr, S,
                                                                SEQ, SEQ, DIM, inv_sqrt_d,
                                                                SEQ * DIM, SEQ * DIM, SEQ * SEQ);
    }

    // 3) softmax (rounds P to tf32)
    softmax2048<<<BATCH * SEQ, 256>>>(S);

    // 4) out = P @ V
    {
        dim3 g(DIM / BN, SEQ / BM, BATCH);
        tgemm<false, false, false><<<g, 128, SMEM_TOTAL_BYTES>>>(S, V, nullptr, out,
                                                                 SEQ, DIM, SEQ, 1.0f,
                                                                 SEQ * SEQ, SEQ * DIM, SEQ * DIM);
    }
}

// round 6
// speedup vs baseline: 5.5302x; 1.6659x over previous
#include <cuda_runtime.h>
#include <cuda_fp16.h>
#include <cstdint>
#include <math.h>

// ---------------------------------------------------------------------------
// SelfAttention, B=4, S=2048, D=1024, fp32 in/out.
// Round 6: fp16 mma.sync m16n8k16 (same 10-bit mantissa as tf32, 2x rate).
// Single uniform NT GEMM: C[m,n] = alpha*sum_k A[m,k]*B[n,k] (+bias).
// W pre-transposed+converted, V transposed (half); scores fp32; P fp16.
// ---------------------------------------------------------------------------

#define BATCH 4
#define SEQ   2048
#define DIM   1024
#define ROWS  (BATCH * SEQ)          // 8192

#define BM 128
#define BN 128
#define BK 32
#define NSTAGES 4

#define TSTRIDE_H   40     // halves per row (32 + 8 pad) -> conflict-free
#define TSTRIDE_W   20     // words per row
#define TILE_WORDS  2560   // 128 * 20
#define STAGE_WORDS 5120   // A + B
#define SMEM_TOTAL_BYTES (NSTAGES * STAGE_WORDS * 4)   // 81920

// ---- scratch (allocation-free rule: device globals) ----
__device__ __half g_xh [(size_t)ROWS * DIM];
__device__ __half g_Wqt[(size_t)DIM * DIM];
__device__ __half g_Wkt[(size_t)DIM * DIM];
__device__ __half g_Wvt[(size_t)DIM * DIM];
__device__ __half g_Q  [(size_t)ROWS * DIM];
__device__ __half g_K  [(size_t)ROWS * DIM];
__device__ __half g_V  [(size_t)ROWS * DIM];
__device__ __half g_Vt [(size_t)ROWS * DIM];
__device__ float  g_S  [(size_t)BATCH * SEQ * SEQ];
__device__ __half g_P  [(size_t)BATCH * SEQ * SEQ];

__device__ __forceinline__ uint32_t smem_u32(const void* p) {
    uint32_t a;
    asm("{ .reg .u64 t; cvta.to.shared.u64 t, %1; cvt.u32.u64 %0, t; }" : "=r"(a) : "l"(p));
    return a;
}
__device__ __forceinline__ void cp_async16(uint32_t dst, const void* src) {
    asm volatile("cp.async.cg.shared.global [%0], [%1], 16;" :: "r"(dst), "l"(src));
}
__device__ __forceinline__ void mma_f16(float* c, const unsigned* a, const unsigned* b) {
    asm volatile(
        "mma.sync.aligned.m16n8k16.row.col.f32.f16.f16.f32 "
        "{%0,%1,%2,%3}, {%4,%5,%6,%7}, {%8,%9}, {%0,%1,%2,%3};"
        : "+f"(c[0]), "+f"(c[1]), "+f"(c[2]), "+f"(c[3])
        : "r"(a[0]), "r"(a[1]), "r"(a[2]), "r"(a[3]), "r"(b[0]), "r"(b[1]));
}

// NT fp16 GEMM: C[z][m,n] = alpha * sum_k A[z][m,k]*B[z][n,k] (+ bias[n]).
// A: [M,K] half; B: [N,K] half. OUT_HALF -> C half, else C float.
// M,N mult of 128; K mult of 32, K/32 >= 3. 256 threads, 2 CTAs/SM.
template <bool BIAS, bool OUT_HALF>
__global__ void __launch_bounds__(256, 2)
hgemm_nt(const __half* __restrict__ A, const __half* __restrict__ B,
         const float* __restrict__ bias, void* __restrict__ Cv,
         int M, int N, int K, float alpha,
         long long sA, long long sB, long long sC)
{
    extern __shared__ uint32_t smw[];
    const uint32_t sb = smem_u32(smw);

    const int tid  = threadIdx.x;
    const int lane = tid & 31;
    const int warp = tid >> 5;
    const int wm   = warp >> 2;   // 0..1
    const int wn   = warp & 3;    // 0..3
    const int qr   = lane >> 2;   // 0..7
    const int qk   = lane & 3;    // 0..3
    const int bm   = blockIdx.y * BM;
    const int bn   = blockIdx.x * BN;

    A += (size_t)blockIdx.z * sA;
    B += (size_t)blockIdx.z * sB;

    // cp.async coords: 256 threads; row = tid>>2 (0..63, +64), kh = (tid&3)*8 halves
    const int ld_row = tid >> 2;
    const int ld_kh  = (tid & 3) * 8;
    const int ld_kw  = (tid & 3) * 4;    // word offset in smem row

    const int T = K / BK;

    auto issue_tile = [&](int t) {
        const int slot = t % NSTAGES;
        const uint32_t a0 = sb + (uint32_t)(slot * STAGE_WORDS) * 4;
        const uint32_t b0 = a0 + TILE_WORDS * 4;
        const int k0 = t * BK;
#pragma unroll
        for (int i = 0; i < 2; i++) {
            int m = ld_row + 64 * i;
            cp_async16(a0 + (uint32_t)(m * TSTRIDE_W + ld_kw) * 4,
                       A + (size_t)(bm + m) * K + k0 + ld_kh);
        }
#pragma unroll
        for (int i = 0; i < 2; i++) {
            int n = ld_row + 64 * i;
            cp_async16(b0 + (uint32_t)(n * TSTRIDE_W + ld_kw) * 4,
                       B + (size_t)(bn + n) * K + k0 + ld_kh);
        }
        asm volatile("cp.async.commit_group;" ::: "memory");
    };

    float acc[4][4][4];
#pragma unroll
    for (int mt = 0; mt < 4; mt++)
#pragma unroll
        for (int nt = 0; nt < 4; nt++)
#pragma unroll
            for (int r = 0; r < 4; r++) acc[mt][nt][r] = 0.0f;

    issue_tile(0); issue_tile(1); issue_tile(2);

    for (int i = 0; i < T; i++) {
        asm volatile("cp.async.wait_group 2;" ::: "memory");
        __syncthreads();

        if (i + 3 < T) issue_tile(i + 3);
        else asm volatile("cp.async.commit_group;" ::: "memory");

        const int slot = i % NSTAGES;
        const uint32_t* As = smw + slot * STAGE_WORDS;
        const uint32_t* Bs = As + TILE_WORDS;
#pragma unroll
        for (int kk = 0; kk < 2; kk++) {
            unsigned af[4][4], bf[4][2];
#pragma unroll
            for (int mt = 0; mt < 4; mt++) {
                const uint32_t* p = As + (wm * 64 + mt * 16 + qr) * TSTRIDE_W + kk * 8 + qk;
                af[mt][0] = p[0];
                af[mt][1] = p[8 * TSTRIDE_W];
                af[mt][2] = p[4];
                af[mt][3] = p[8 * TSTRIDE_W + 4];
            }
#pragma unroll
            for (int nt = 0; nt < 4; nt++) {
                const uint32_t* q = Bs + (wn * 32 + nt * 8 + qr) * TSTRIDE_W + kk * 8 + qk;
                bf[nt][0] = q[0];
                bf[nt][1] = q[4];
            }
#pragma unroll
            for (int mt = 0; mt < 4; mt++)
#pragma unroll
                for (int nt = 0; nt < 4; nt++)
                    mma_f16(acc[mt][nt], af[mt], bf[nt]);
        }
    }

    // ---- epilogue
#pragma unroll
    for (int mt = 0; mt < 4; mt++) {
        int r0 = bm + wm * 64 + mt * 16 + qr;
#pragma unroll
        for (int nt = 0; nt < 4; nt++) {
            int c = bn + wn * 32 + nt * 8 + qk * 2;
            float v00 = acc[mt][nt][0] * alpha;
            float v01 = acc[mt][nt][1] * alpha;
            float v10 = acc[mt][nt][2] * alpha;
            float v11 = acc[mt][nt][3] * alpha;
            if (BIAS) {
                float b0 = bias[c], b1 = bias[c + 1];
                v00 += b0; v01 += b1;
                v10 += b0; v11 += b1;
            }
            if (OUT_HALF) {
                __half* C = (__half*)Cv + (size_t)blockIdx.z * sC;
                __half2 h0 = __floats2half2_rn(v00, v01);
                __half2 h1 = __floats2half2_rn(v10, v11);
                *(__half2*)(C + (size_t)r0 * N + c)       = h0;
                *(__half2*)(C + (size_t)(r0 + 8) * N + c) = h1;
            } else {
                float* C = (float*)Cv + (size_t)blockIdx.z * sC;
                *(float2*)(C + (size_t)r0 * N + c)       = make_float2(v00, v01);
                *(float2*)(C + (size_t)(r0 + 8) * N + c) = make_float2(v10, v11);
            }
        }
    }
}

// float -> half conversion, 8 elems/thread
__global__ void __launch_bounds__(256)
f2h8(const float4* __restrict__ in, uint4* __restrict__ out, int n8)
{
    int i = blockIdx.x * 256 + threadIdx.x;
    if (i < n8) {
        float4 a = in[2 * i], b = in[2 * i + 1];
        __half2 h0 = __floats2half2_rn(a.x, a.y);
        __half2 h1 = __floats2half2_rn(a.z, a.w);
        __half2 h2 = __floats2half2_rn(b.x, b.y);
        __half2 h3 = __floats2half2_rn(b.z, b.w);
        uint4 o;
        o.x = *(unsigned*)&h0; o.y = *(unsigned*)&h1;
        o.z = *(unsigned*)&h2; o.w = *(unsigned*)&h3;
        out[i] = o;
    }
}

// out[c][r] = half(in[r][c]); in [R,C] float row-major
__global__ void __launch_bounds__(256)
transpose_f2h(const float* __restrict__ in, __half* __restrict__ out, int R, int C)
{
    __shared__ float t[32][33];
    int c0 = blockIdx.x * 32, r0 = blockIdx.y * 32;
    int tx = threadIdx.x, ty = threadIdx.y;
#pragma unroll
    for (int i = 0; i < 32; i += 8)
        t[ty + i][tx] = in[(size_t)(r0 + ty + i) * C + c0 + tx];
    __syncthreads();
#pragma unroll
    for (int i = 0; i < 32; i += 8)
        out[(size_t)(c0 + ty + i) * R + r0 + tx] = __float2half(t[tx][ty + i]);
}

// out[z][c][r] = in[z][r][c]; in [R,C] half row-major per batch
__global__ void __launch_bounds__(256)
transpose_h(const __half* __restrict__ in, __half* __restrict__ out, int R, int C)
{
    __shared__ __half t[32][33];
    const __half* ip = in + (size_t)blockIdx.z * R * C;
    __half* op = out + (size_t)blockIdx.z * R * C;
    int c0 = blockIdx.x * 32, r0 = blockIdx.y * 32;
    int tx = threadIdx.x, ty = threadIdx.y;
#pragma unroll
    for (int i = 0; i < 32; i += 8)
        t[ty + i][tx] = ip[(size_t)(r0 + ty + i) * C + c0 + tx];
    __syncthreads();
#pragma unroll
    for (int i = 0; i < 32; i += 8)
        op[(size_t)(c0 + ty + i) * R + r0 + tx] = t[tx][ty + i];
}

// softmax over rows of 2048: fp32 in -> fp16 out
__global__ void __launch_bounds__(256)
softmax2048h(const float* __restrict__ S, __half* __restrict__ P)
{
    __shared__ float red_max[8];
    __shared__ float red_sum[8];
    const float* p = S + (size_t)blockIdx.x * 2048;
    __half* o = P + (size_t)blockIdx.x * 2048;
    const int t = threadIdx.x;

    float4 v0 = ((const float4*)p)[t];
    float4 v1 = ((const float4*)p)[t + 256];

    float m = fmaxf(fmaxf(fmaxf(v0.x, v0.y), fmaxf(v0.z, v0.w)),
                    fmaxf(fmaxf(v1.x, v1.y), fmaxf(v1.z, v1.w)));
#pragma unroll
    for (int off = 16; off; off >>= 1) m = fmaxf(m, __shfl_xor_sync(0xffffffffu, m, off));
    if ((t & 31) == 0) red_max[t >> 5] = m;
    __syncthreads();
    m = red_max[0];
#pragma unroll
    for (int w = 1; w < 8; w++) m = fmaxf(m, red_max[w]);

    v0.x = expf(v0.x - m); v0.y = expf(v0.y - m);
    v0.z = expf(v0.z - m); v0.w = expf(v0.w - m);
    v1.x = expf(v1.x - m); v1.y = expf(v1.y - m);
    v1.z = expf(v1.z - m); v1.w = expf(v1.w - m);

    float s = (v0.x + v0.y + v0.z + v0.w) + (v1.x + v1.y + v1.z + v1.w);
#pragma unroll
    for (int off = 16; off; off >>= 1) s += __shfl_xor_sync(0xffffffffu, s, off);
    if ((t & 31) == 0) red_sum[t >> 5] = s;
    __syncthreads();
    s = red_sum[0];
#pragma unroll
    for (int w = 1; w < 8; w++) s += red_sum[w];

    float inv = 1.0f / s;
    __half2 h0 = __floats2half2_rn(v0.x * inv, v0.y * inv);
    __half2 h1 = __floats2half2_rn(v0.z * inv, v0.w * inv);
    __half2 h2 = __floats2half2_rn(v1.x * inv, v1.y * inv);
    __half2 h3 = __floats2half2_rn(v1.z * inv, v1.w * inv);
    uint2 o0, o1;
    o0.x = *(unsigned*)&h0; o0.y = *(unsigned*)&h1;
    o1.x = *(unsigned*)&h2; o1.y = *(unsigned*)&h3;
    ((uint2*)o)[t]       = o0;
    ((uint2*)o)[t + 256] = o1;
}

extern "C" void kernel_launch(void* const* d_in, const int* in_sizes, int n_in,
                              void* d_out, int out_size)
{
    (void)in_sizes; (void)n_in; (void)out_size;
    const float* x  = (const float*)d_in[0];
    const float* Wq = (const float*)d_in[1];
    const float* bq = (const float*)d_in[2];
    const float* Wk = (const float*)d_in[3];
    const float* bk = (const float*)d_in[4];
    const float* Wv = (const float*)d_in[5];
    const float* bv = (const float*)d_in[6];
    float* out = (float*)d_out;

    __half *xh, *Wqt, *Wkt, *Wvt, *Q, *K, *V, *Vt, *P;
    float* S;
    cudaGetSymbolAddress((void**)&xh,  g_xh);
    cudaGetSymbolAddress((void**)&Wqt, g_Wqt);
    cudaGetSymbolAddress((void**)&Wkt, g_Wkt);
    cudaGetSymbolAddress((void**)&Wvt, g_Wvt);
    cudaGetSymbolAddress((void**)&Q,   g_Q);
    cudaGetSymbolAddress((void**)&K,   g_K);
    cudaGetSymbolAddress((void**)&V,   g_V);
    cudaGetSymbolAddress((void**)&Vt,  g_Vt);
    cudaGetSymbolAddress((void**)&S,   g_S);
    cudaGetSymbolAddress((void**)&P,   g_P);

    cudaFuncSetAttribute(hgemm_nt<true,  true >,
                         cudaFuncAttributeMaxDynamicSharedMemorySize, SMEM_TOTAL_BYTES);
    cudaFuncSetAttribute(hgemm_nt<false, false>,
                         cudaFuncAttributeMaxDynamicSharedMemorySize, SMEM_TOTAL_BYTES);

    // 0) conversions: x -> half; W -> half transposed
    f2h8<<<ROWS * DIM / 8 / 256, 256>>>((const float4*)x, (uint4*)xh, ROWS * DIM / 8);
    {
        dim3 g(DIM / 32, DIM / 32, 1), b(32, 8);
        transpose_f2h<<<g, b>>>(Wq, Wqt, DIM, DIM);
        transpose_f2h<<<g, b>>>(Wk, Wkt, DIM, DIM);
        transpose_f2h<<<g, b>>>(Wv, Wvt, DIM, DIM);
    }

    // 1) QKV projections (half out)
    {
        dim3 g(DIM / BN, ROWS / BM, 1);
        hgemm_nt<true, true><<<g, 256, SMEM_TOTAL_BYTES>>>(xh, Wqt, bq, Q, ROWS, DIM, DIM, 1.0f, 0, 0, 0);
        hgemm_nt<true, true><<<g, 256, SMEM_TOTAL_BYTES>>>(xh, Wkt, bk, K, ROWS, DIM, DIM, 1.0f, 0, 0, 0);
        hgemm_nt<true, true><<<g, 256, SMEM_TOTAL_BYTES>>>(xh, Wvt, bv, V, ROWS, DIM, DIM, 1.0f, 0, 0, 0);
    }

    // 2) V -> Vt (per-batch transpose, half)
    {
        dim3 g(DIM / 32, SEQ / 32, BATCH), b(32, 8);
        transpose_h<<<g, b>>>(V, Vt, SEQ, DIM);
    }

    // 3) scores = Q @ K^T / 32 (float out)
    {
        dim3 g(SEQ / BN, SEQ / BM, BATCH);
        hgemm_nt<false, false><<<g, 256, SMEM_TOTAL_BYTES>>>(Q, K, nullptr, S,
                                                             SEQ, SEQ, DIM, 0.03125f,
                                                             (long long)SEQ * DIM, (long long)SEQ * DIM,
                                                             (long long)SEQ * SEQ);
    }

    // 4) softmax -> fp16 P
    softmax2048h<<<BATCH * SEQ, 256>>>(S, P);

    // 5) out = P @ Vt^T (float out)
    {
        dim3 g(DIM / BN, SEQ / BM, BATCH);
        hgemm_nt<false, false><<<g, 256, SMEM_TOTAL_BYTES>>>(P, Vt, nullptr, out,
                                                             SEQ, DIM, SEQ, 1.0f,
                                                             (long long)SEQ * SEQ, (long long)SEQ * DIM,
                                                             (long long)SEQ * DIM);
    }
}

// round 7
// speedup vs baseline: 5.8470x; 1.0573x over previous
#include <cuda_runtime.h>
#include <cuda_fp16.h>
#include <cstdint>
#include <math.h>

// ---------------------------------------------------------------------------
// SelfAttention, B=4, S=2048, D=1024, fp32 in/out.
// Round 7: fp16 mma.sync m16n8k16 + ldmatrix fragment loads + fused QKV GEMM.
// Uniform NT GEMM with row strides: C[m,n] = alpha*sum_k A[m,k]B[n,k] (+bias).
// ---------------------------------------------------------------------------

#define BATCH 4
#define SEQ   2048
#define DIM   1024
#define ROWS  (BATCH * SEQ)          // 8192
#define QKVN  (3 * DIM)              // 3072

#define BM 128
#define BN 128
#define BK 32
#define NSTAGES 4

#define TSTRIDE_H   40     // halves per smem row (32 + 8 pad)
#define TSTRIDE_W   20
#define TILE_WORDS  2560   // 128 * 20
#define STAGE_WORDS 5120
#define STAGE_BYTES 20480
#define SMEM_TOTAL_BYTES (NSTAGES * STAGE_WORDS * 4)   // 81920

// ---- scratch (allocation-free rule: device globals) ----
__device__ __half g_xh  [(size_t)ROWS * DIM];
__device__ __half g_WT  [(size_t)QKVN * DIM];     // [Wq^T; Wk^T; Wv^T]
__device__ float  g_bias[QKVN];
__device__ __half g_QKV [(size_t)ROWS * QKVN];
__device__ __half g_Vt  [(size_t)ROWS * DIM];
__device__ float  g_S   [(size_t)BATCH * SEQ * SEQ];
__device__ __half g_P   [(size_t)BATCH * SEQ * SEQ];

__device__ __forceinline__ uint32_t smem_u32(const void* p) {
    uint32_t a;
    asm("{ .reg .u64 t; cvta.to.shared.u64 t, %1; cvt.u32.u64 %0, t; }" : "=r"(a) : "l"(p));
    return a;
}
__device__ __forceinline__ void cp_async16(uint32_t dst, const void* src) {
    asm volatile("cp.async.cg.shared.global [%0], [%1], 16;" :: "r"(dst), "l"(src));
}
__device__ __forceinline__ void mma_f16(float* c, const unsigned* a, const unsigned* b) {
    asm volatile(
        "mma.sync.aligned.m16n8k16.row.col.f32.f16.f16.f32 "
        "{%0,%1,%2,%3}, {%4,%5,%6,%7}, {%8,%9}, {%0,%1,%2,%3};"
        : "+f"(c[0]), "+f"(c[1]), "+f"(c[2]), "+f"(c[3])
        : "r"(a[0]), "r"(a[1]), "r"(a[2]), "r"(a[3]), "r"(b[0]), "r"(b[1]));
}
__device__ __forceinline__ void ldsm_x4(unsigned* r, uint32_t addr) {
    asm volatile("ldmatrix.sync.aligned.m8n8.x4.shared.b16 {%0,%1,%2,%3}, [%4];"
                 : "=r"(r[0]), "=r"(r[1]), "=r"(r[2]), "=r"(r[3]) : "r"(addr));
}
__device__ __forceinline__ void ldsm_x2(unsigned* r, uint32_t addr) {
    asm volatile("ldmatrix.sync.aligned.m8n8.x2.shared.b16 {%0,%1}, [%2];"
                 : "=r"(r[0]), "=r"(r[1]) : "r"(addr));
}

// NT fp16 GEMM with row strides: C[z][m,n] = alpha*sum_k A[m,k]B[n,k] (+bias[n]).
// M,N mult of 128; K mult of 32, K/32 >= 3. 256 threads, 2 CTAs/SM.
template <bool BIAS, bool OUT_HALF>
__global__ void __launch_bounds__(256, 2)
hgemm_nt(const __half* __restrict__ A, int lda,
         const __half* __restrict__ B, int ldb,
         const float* __restrict__ bias, void* __restrict__ Cv, int ldc,
         int N, int K, float alpha,
         long long sA, long long sB, long long sC)
{
    extern __shared__ uint32_t smw[];
    const uint32_t sb = smem_u32(smw);

    const int tid  = threadIdx.x;
    const int lane = tid & 31;
    const int warp = tid >> 5;
    const int wm   = warp >> 2;   // 0..1
    const int wn   = warp & 3;    // 0..3
    const int qr   = lane >> 2;
    const int qk   = lane & 3;
    const int bm   = blockIdx.y * BM;
    const int bn   = blockIdx.x * BN;

    A += (size_t)blockIdx.z * sA;
    B += (size_t)blockIdx.z * sB;

    // cp.async coords
    const int ld_row = tid >> 2;          // 0..63 (+64)
    const int ld_kh  = (tid & 3) * 8;
    const int ld_kw  = (tid & 3) * 4;

    // ldmatrix per-thread byte offsets within a stage
    uint32_t offA[4], offB[4];
#pragma unroll
    for (int mt = 0; mt < 4; mt++) {
        int row  = wm * 64 + mt * 16 + (lane & 15);
        int colh = (lane >> 4) * 8;
        offA[mt] = (uint32_t)(row * TSTRIDE_H + colh) * 2;
    }
#pragma unroll
    for (int nt = 0; nt < 4; nt++) {
        int row  = wn * 32 + nt * 8 + (lane & 7);
        int colh = ((lane >> 3) & 1) * 8;
        offB[nt] = (uint32_t)(row * TSTRIDE_H + colh) * 2 + TILE_WORDS * 4;
    }

    const int T = K / BK;

    auto issue_tile = [&](int t) {
        const int slot = t % NSTAGES;
        const uint32_t a0 = sb + (uint32_t)slot * STAGE_BYTES;
        const uint32_t b0 = a0 + TILE_WORDS * 4;
        const int k0 = t * BK;
#pragma unroll
        for (int i = 0; i < 2; i++) {
            int m = ld_row + 64 * i;
            cp_async16(a0 + (uint32_t)(m * TSTRIDE_W + ld_kw) * 4,
                       A + (size_t)(bm + m) * lda + k0 + ld_kh);
        }
#pragma unroll
        for (int i = 0; i < 2; i++) {
            int n = ld_row + 64 * i;
            cp_async16(b0 + (uint32_t)(n * TSTRIDE_W + ld_kw) * 4,
                       B + (size_t)(bn + n) * ldb + k0 + ld_kh);
        }
        asm volatile("cp.async.commit_group;" ::: "memory");
    };

    float acc[4][4][4];
#pragma unroll
    for (int mt = 0; mt < 4; mt++)
#pragma unroll
        for (int nt = 0; nt < 4; nt++)
#pragma unroll
            for (int r = 0; r < 4; r++) acc[mt][nt][r] = 0.0f;

    issue_tile(0); issue_tile(1); issue_tile(2);

    for (int i = 0; i < T; i++) {
        asm volatile("cp.async.wait_group 2;" ::: "memory");
        __syncthreads();

        if (i + 3 < T) issue_tile(i + 3);
        else asm volatile("cp.async.commit_group;" ::: "memory");

        const uint32_t st = sb + (uint32_t)(i % NSTAGES) * STAGE_BYTES;
#pragma unroll
        for (int kk = 0; kk < 2; kk++) {
            const uint32_t kof = st + kk * 32;   // 16 halves = 32 bytes
            unsigned af[4][4], bf[4][2];
#pragma unroll
            for (int mt = 0; mt < 4; mt++) ldsm_x4(af[mt], kof + offA[mt]);
#pragma unroll
            for (int nt = 0; nt < 4; nt++) ldsm_x2(bf[nt], kof + offB[nt]);
#pragma unroll
            for (int mt = 0; mt < 4; mt++)
#pragma unroll
                for (int nt = 0; nt < 4; nt++)
                    mma_f16(acc[mt][nt], af[mt], bf[nt]);
        }
    }

    // ---- epilogue
#pragma unroll
    for (int mt = 0; mt < 4; mt++) {
        int r0 = bm + wm * 64 + mt * 16 + qr;
#pragma unroll
        for (int nt = 0; nt < 4; nt++) {
            int c = bn + wn * 32 + nt * 8 + qk * 2;
            float v00 = acc[mt][nt][0] * alpha;
            float v01 = acc[mt][nt][1] * alpha;
            float v10 = acc[mt][nt][2] * alpha;
            float v11 = acc[mt][nt][3] * alpha;
            if (BIAS) {
                float b0 = bias[c], b1 = bias[c + 1];
                v00 += b0; v01 += b1;
                v10 += b0; v11 += b1;
            }
            if (OUT_HALF) {
                __half* C = (__half*)Cv + (size_t)blockIdx.z * sC;
                *(__half2*)(C + (size_t)r0 * ldc + c)       = __floats2half2_rn(v00, v01);
                *(__half2*)(C + (size_t)(r0 + 8) * ldc + c) = __floats2half2_rn(v10, v11);
            } else {
                float* C = (float*)Cv + (size_t)blockIdx.z * sC;
                *(float2*)(C + (size_t)r0 * ldc + c)       = make_float2(v00, v01);
                *(float2*)(C + (size_t)(r0 + 8) * ldc + c) = make_float2(v10, v11);
            }
        }
    }
}

// float -> half, 8 elems/thread
__global__ void __launch_bounds__(256)
f2h8(const float4* __restrict__ in, uint4* __restrict__ out, int n8)
{
    int i = blockIdx.x * 256 + threadIdx.x;
    if (i < n8) {
        float4 a = in[2 * i], b = in[2 * i + 1];
        __half2 h0 = __floats2half2_rn(a.x, a.y);
        __half2 h1 = __floats2half2_rn(a.z, a.w);
        __half2 h2 = __floats2half2_rn(b.x, b.y);
        __half2 h3 = __floats2half2_rn(b.z, b.w);
        uint4 o;
        o.x = *(unsigned*)&h0; o.y = *(unsigned*)&h1;
        o.z = *(unsigned*)&h2; o.w = *(unsigned*)&h3;
        out[i] = o;
    }
}

// out[c][r] = half(in[r][c]); in [R,C] float row-major
__global__ void __launch_bounds__(256)
transpose_f2h(const float* __restrict__ in, __half* __restrict__ out, int R, int C)
{
    __shared__ float t[32][33];
    int c0 = blockIdx.x * 32, r0 = blockIdx.y * 32;
    int tx = threadIdx.x, ty = threadIdx.y;
#pragma unroll
    for (int i = 0; i < 32; i += 8)
        t[ty + i][tx] = in[(size_t)(r0 + ty + i) * C + c0 + tx];
    __syncthreads();
#pragma unroll
    for (int i = 0; i < 32; i += 8)
        out[(size_t)(c0 + ty + i) * R + r0 + tx] = __float2half(t[tx][ty + i]);
}

// Vt[z][c][r] = V[z][r][c], V rows strided by ldin (view into QKV)
__global__ void __launch_bounds__(256)
transpose_h_strided(const __half* __restrict__ in, int ldin,
                    __half* __restrict__ out, int R, int C)
{
    __shared__ __half t[32][33];
    const __half* ip = in + (size_t)blockIdx.z * R * ldin;
    __half* op = out + (size_t)blockIdx.z * R * C;
    int c0 = blockIdx.x * 32, r0 = blockIdx.y * 32;
    int tx = threadIdx.x, ty = threadIdx.y;
#pragma unroll
    for (int i = 0; i < 32; i += 8)
        t[ty + i][tx] = ip[(size_t)(r0 + ty + i) * ldin + c0 + tx];
    __syncthreads();
#pragma unroll
    for (int i = 0; i < 32; i += 8)
        op[(size_t)(c0 + ty + i) * R + r0 + tx] = t[tx][ty + i];
}

// softmax over rows of 2048: fp32 in -> fp16 out
__global__ void __launch_bounds__(256)
softmax2048h(const float* __restrict__ S, __half* __restrict__ P)
{
    __shared__ float red_max[8];
    __shared__ float red_sum[8];
    const float* p = S + (size_t)blockIdx.x * 2048;
    __half* o = P + (size_t)blockIdx.x * 2048;
    const int t = threadIdx.x;

    float4 v0 = ((const float4*)p)[t];
    float4 v1 = ((const float4*)p)[t + 256];

    float m = fmaxf(fmaxf(fmaxf(v0.x, v0.y), fmaxf(v0.z, v0.w)),
                    fmaxf(fmaxf(v1.x, v1.y), fmaxf(v1.z, v1.w)));
#pragma unroll
    for (int off = 16; off; off >>= 1) m = fmaxf(m, __shfl_xor_sync(0xffffffffu, m, off));
    if ((t & 31) == 0) red_max[t >> 5] = m;
    __syncthreads();
    m = red_max[0];
#pragma unroll
    for (int w = 1; w < 8; w++) m = fmaxf(m, red_max[w]);

    v0.x = expf(v0.x - m); v0.y = expf(v0.y - m);
    v0.z = expf(v0.z - m); v0.w = expf(v0.w - m);
    v1.x = expf(v1.x - m); v1.y = expf(v1.y - m);
    v1.z = expf(v1.z - m); v1.w = expf(v1.w - m);

    float s = (v0.x + v0.y + v0.z + v0.w) + (v1.x + v1.y + v1.z + v1.w);
#pragma unroll
    for (int off = 16; off; off >>= 1) s += __shfl_xor_sync(0xffffffffu, s, off);
    if ((t & 31) == 0) red_sum[t >> 5] = s;
    __syncthreads();
    s = red_sum[0];
#pragma unroll
    for (int w = 1; w < 8; w++) s += red_sum[w];

    float inv = 1.0f / s;
    __half2 h0 = __floats2half2_rn(v0.x * inv, v0.y * inv);
    __half2 h1 = __floats2half2_rn(v0.z * inv, v0.w * inv);
    __half2 h2 = __floats2half2_rn(v1.x * inv, v1.y * inv);
    __half2 h3 = __floats2half2_rn(v1.z * inv, v1.w * inv);
    uint2 o0, o1;
    o0.x = *(unsigned*)&h0; o0.y = *(unsigned*)&h1;
    o1.x = *(unsigned*)&h2; o1.y = *(unsigned*)&h3;
    ((uint2*)o)[t]       = o0;
    ((uint2*)o)[t + 256] = o1;
}

extern "C" void kernel_launch(void* const* d_in, const int* in_sizes, int n_in,
                              void* d_out, int out_size)
{
    (void)in_sizes; (void)n_in; (void)out_size;
    const float* x  = (const float*)d_in[0];
    const float* Wq = (const float*)d_in[1];
    const float* bq = (const float*)d_in[2];
    const float* Wk = (const float*)d_in[3];
    const float* bk = (const float*)d_in[4];
    const float* Wv = (const float*)d_in[5];
    const float* bv = (const float*)d_in[6];
    float* out = (float*)d_out;

    __half *xh, *WT, *QKV, *Vt, *P;
    float *S, *biasAll;
    cudaGetSymbolAddress((void**)&xh,      g_xh);
    cudaGetSymbolAddress((void**)&WT,      g_WT);
    cudaGetSymbolAddress((void**)&biasAll, g_bias);
    cudaGetSymbolAddress((void**)&QKV,     g_QKV);
    cudaGetSymbolAddress((void**)&Vt,      g_Vt);
    cudaGetSymbolAddress((void**)&S,       g_S);
    cudaGetSymbolAddress((void**)&P,       g_P);

    cudaFuncSetAttribute(hgemm_nt<true,  true >,
                         cudaFuncAttributeMaxDynamicSharedMemorySize, SMEM_TOTAL_BYTES);
    cudaFuncSetAttribute(hgemm_nt<false, false>,
                         cudaFuncAttributeMaxDynamicSharedMemorySize, SMEM_TOTAL_BYTES);

    // 0) prep: x->half; W->half transposed into combined WT; combined bias
    f2h8<<<ROWS * DIM / 8 / 256, 256>>>((const float4*)x, (uint4*)xh, ROWS * DIM / 8);
    {
        dim3 g(DIM / 32, DIM / 32, 1), b(32, 8);
        transpose_f2h<<<g, b>>>(Wq, WT,                           DIM, DIM);
        transpose_f2h<<<g, b>>>(Wk, WT + (size_t)DIM * DIM,       DIM, DIM);
        transpose_f2h<<<g, b>>>(Wv, WT + (size_t)2 * DIM * DIM,   DIM, DIM);
    }
    cudaMemcpyAsync(biasAll,            bq, DIM * sizeof(float), cudaMemcpyDeviceToDevice);
    cudaMemcpyAsync(biasAll + DIM,      bk, DIM * sizeof(float), cudaMemcpyDeviceToDevice);
    cudaMemcpyAsync(biasAll + 2 * DIM,  bv, DIM * sizeof(float), cudaMemcpyDeviceToDevice);

    // 1) fused QKV projection: [8192,1024] @ WT[3072,1024]^T -> QKV [8192,3072]
    {
        dim3 g(QKVN / BN, ROWS / BM, 1);
        hgemm_nt<true, true><<<g, 256, SMEM_TOTAL_BYTES>>>(
            xh, DIM, WT, DIM, biasAll, QKV, QKVN, QKVN, DIM, 1.0f, 0, 0, 0);
    }

    // 2) V (QKV cols 2048..3071) -> Vt per batch
    {
        dim3 g(DIM / 32, SEQ / 32, BATCH), b(32, 8);
        transpose_h_strided<<<g, b>>>(QKV + 2 * DIM, QKVN, Vt, SEQ, DIM);
    }

    // 3) scores = Q @ K^T / 32 (float out)
    {
        dim3 g(SEQ / BN, SEQ / BM, BATCH);
        hgemm_nt<false, false><<<g, 256, SMEM_TOTAL_BYTES>>>(
            QKV, QKVN, QKV + DIM, QKVN, nullptr, S, SEQ,
            SEQ, DIM, 0.03125f,
            (long long)SEQ * QKVN, (long long)SEQ * QKVN, (long long)SEQ * SEQ);
    }

    // 4) softmax -> fp16 P
    softmax2048h<<<BATCH * SEQ, 256>>>(S, P);

    // 5) out = P @ Vt^T (float out)
    {
        dim3 g(DIM / BN, SEQ / BM, BATCH);
        hgemm_nt<false, false><<<g, 256, SMEM_TOTAL_BYTES>>>(
            P, SEQ, Vt, SEQ, nullptr, out, DIM,
            DIM, SEQ, 1.0f,
            (long long)SEQ * SEQ, (long long)SEQ * DIM, (long long)SEQ * DIM);
    }
}

// round 8
// speedup vs baseline: 7.0825x; 1.2113x over previous
#include <cuda_runtime.h>
#include <cuda_fp16.h>
#include <cstdint>
#include <math.h>

// ---------------------------------------------------------------------------
// SelfAttention, B=4, S=2048, D=1024, fp32 in/out.
// Round 8: fp16 m16n8k16; BK=64 / 3-stage cp.async pipeline (half the syncs);
// B fragments via ldmatrix.x4; fused QKV projection.
// ---------------------------------------------------------------------------

#define BATCH 4
#define SEQ   2048
#define DIM   1024
#define ROWS  (BATCH * SEQ)          // 8192
#define QKVN  (3 * DIM)              // 3072

#define BM 128
#define BN 128
#define BK 64
#define NSTAGES 3

#define TSTRIDE_H   72     // halves per smem row (64 + 8 pad) -> conflict-free
#define TILE_BYTES  18432  // 128 * 72 * 2
#define STAGE_BYTES 36864
#define SMEM_TOTAL_BYTES (NSTAGES * STAGE_BYTES)   // 110592

// ---- scratch (allocation-free rule: device globals) ----
__device__ __half g_xh  [(size_t)ROWS * DIM];
__device__ __half g_WT  [(size_t)QKVN * DIM];     // [Wq^T; Wk^T; Wv^T]
__device__ float  g_bias[QKVN];
__device__ __half g_QKV [(size_t)ROWS * QKVN];
__device__ __half g_Vt  [(size_t)ROWS * DIM];
__device__ float  g_S   [(size_t)BATCH * SEQ * SEQ];
__device__ __half g_P   [(size_t)BATCH * SEQ * SEQ];

__device__ __forceinline__ uint32_t smem_u32(const void* p) {
    uint32_t a;
    asm("{ .reg .u64 t; cvta.to.shared.u64 t, %1; cvt.u32.u64 %0, t; }" : "=r"(a) : "l"(p));
    return a;
}
__device__ __forceinline__ void cp_async16(uint32_t dst, const void* src) {
    asm volatile("cp.async.cg.shared.global [%0], [%1], 16;" :: "r"(dst), "l"(src));
}
__device__ __forceinline__ void mma_f16(float* c, const unsigned* a, const unsigned* b) {
    asm volatile(
        "mma.sync.aligned.m16n8k16.row.col.f32.f16.f16.f32 "
        "{%0,%1,%2,%3}, {%4,%5,%6,%7}, {%8,%9}, {%0,%1,%2,%3};"
        : "+f"(c[0]), "+f"(c[1]), "+f"(c[2]), "+f"(c[3])
        : "r"(a[0]), "r"(a[1]), "r"(a[2]), "r"(a[3]), "r"(b[0]), "r"(b[1]));
}
__device__ __forceinline__ void ldsm_x4(unsigned* r, uint32_t addr) {
    asm volatile("ldmatrix.sync.aligned.m8n8.x4.shared.b16 {%0,%1,%2,%3}, [%4];"
                 : "=r"(r[0]), "=r"(r[1]), "=r"(r[2]), "=r"(r[3]) : "r"(addr));
}

// NT fp16 GEMM with row strides: C[z][m,n] = alpha*sum_k A[m,k]B[n,k] (+bias[n]).
// M,N mult of 128; K mult of 64, K/64 >= 2. 256 threads, 2 CTAs/SM.
template <bool BIAS, bool OUT_HALF>
__global__ void __launch_bounds__(256, 2)
hgemm_nt(const __half* __restrict__ A, int lda,
         const __half* __restrict__ B, int ldb,
         const float* __restrict__ bias, void* __restrict__ Cv, int ldc,
         int N, int K, float alpha,
         long long sA, long long sB, long long sC)
{
    extern __shared__ uint32_t smw[];
    const uint32_t sb = smem_u32(smw);

    const int tid  = threadIdx.x;
    const int lane = tid & 31;
    const int warp = tid >> 5;
    const int wm   = warp >> 2;   // 0..1
    const int wn   = warp & 3;    // 0..3
    const int qr   = lane >> 2;
    const int qk   = lane & 3;
    const int bm   = blockIdx.y * BM;
    const int bn   = blockIdx.x * BN;

    A += (size_t)blockIdx.z * sA;
    B += (size_t)blockIdx.z * sB;

    // cp.async coords: 128B rows, 8 threads x 16B per row; 32 rows per pass, 4 passes
    const int ld_row = tid >> 3;          // 0..31
    const int ld_kh  = (tid & 7) * 8;     // halves

    // ldmatrix offsets (bytes, within stage)
    // A x4 (m16 x k16): row = wm*64 + mt*16 + (lane&15), colh = (lane>>4)*8
    uint32_t offA[4];
#pragma unroll
    for (int mt = 0; mt < 4; mt++) {
        int row  = wm * 64 + mt * 16 + (lane & 15);
        int colh = (lane >> 4) * 8;
        offA[mt] = (uint32_t)(row * TSTRIDE_H + colh) * 2;
    }
    // B x4 (two n8 tiles x k16): matrices 0,1 -> nt=2p (col halves 0,1); 2,3 -> nt=2p+1
    uint32_t offB[2];
#pragma unroll
    for (int p = 0; p < 2; p++) {
        int m    = lane >> 3;             // 0..3
        int row  = wn * 32 + p * 16 + (m >> 1) * 8 + (lane & 7);
        int colh = (m & 1) * 8;
        offB[p]  = (uint32_t)(row * TSTRIDE_H + colh) * 2 + TILE_BYTES;
    }

    const int T = K / BK;

    auto issue_tile = [&](int t) {
        const int slot = t % NSTAGES;
        const uint32_t a0 = sb + (uint32_t)slot * STAGE_BYTES;
        const uint32_t b0 = a0 + TILE_BYTES;
        const int k0 = t * BK;
#pragma unroll
        for (int i = 0; i < 4; i++) {
            int m = ld_row + 32 * i;
            cp_async16(a0 + (uint32_t)(m * TSTRIDE_H + ld_kh) * 2,
                       A + (size_t)(bm + m) * lda + k0 + ld_kh);
        }
#pragma unroll
        for (int i = 0; i < 4; i++) {
            int n = ld_row + 32 * i;
            cp_async16(b0 + (uint32_t)(n * TSTRIDE_H + ld_kh) * 2,
                       B + (size_t)(bn + n) * ldb + k0 + ld_kh);
        }
        asm volatile("cp.async.commit_group;" ::: "memory");
    };

    float acc[4][4][4];
#pragma unroll
    for (int mt = 0; mt < 4; mt++)
#pragma unroll
        for (int nt = 0; nt < 4; nt++)
#pragma unroll
            for (int r = 0; r < 4; r++) acc[mt][nt][r] = 0.0f;

    issue_tile(0); issue_tile(1);

    for (int i = 0; i < T; i++) {
        asm volatile("cp.async.wait_group 1;" ::: "memory");
        __syncthreads();

        if (i + 2 < T) issue_tile(i + 2);
        else asm volatile("cp.async.commit_group;" ::: "memory");

        const uint32_t st = sb + (uint32_t)(i % NSTAGES) * STAGE_BYTES;
#pragma unroll
        for (int kk = 0; kk < 4; kk++) {           // 4 x k16 per BK=64 stage
            const uint32_t kof = st + kk * 32;     // 16 halves = 32 B
            unsigned af[4][4], bf[2][4];
#pragma unroll
            for (int mt = 0; mt < 4; mt++) ldsm_x4(af[mt], kof + offA[mt]);
#pragma unroll
            for (int p = 0; p < 2; p++)  ldsm_x4(bf[p], kof + offB[p]);
#pragma unroll
            for (int mt = 0; mt < 4; mt++) {
                mma_f16(acc[mt][0], af[mt], &bf[0][0]);
                mma_f16(acc[mt][1], af[mt], &bf[0][2]);
                mma_f16(acc[mt][2], af[mt], &bf[1][0]);
                mma_f16(acc[mt][3], af[mt], &bf[1][2]);
            }
        }
    }

    // ---- epilogue
#pragma unroll
    for (int mt = 0; mt < 4; mt++) {
        int r0 = bm + wm * 64 + mt * 16 + qr;
#pragma unroll
        for (int nt = 0; nt < 4; nt++) {
            int c = bn + wn * 32 + nt * 8 + qk * 2;
            float v00 = acc[mt][nt][0] * alpha;
            float v01 = acc[mt][nt][1] * alpha;
            float v10 = acc[mt][nt][2] * alpha;
            float v11 = acc[mt][nt][3] * alpha;
            if (BIAS) {
                float b0 = bias[c], b1 = bias[c + 1];
                v00 += b0; v01 += b1;
                v10 += b0; v11 += b1;
            }
            if (OUT_HALF) {
                __half* C = (__half*)Cv + (size_t)blockIdx.z * sC;
                *(__half2*)(C + (size_t)r0 * ldc + c)       = __floats2half2_rn(v00, v01);
                *(__half2*)(C + (size_t)(r0 + 8) * ldc + c) = __floats2half2_rn(v10, v11);
            } else {
                float* C = (float*)Cv + (size_t)blockIdx.z * sC;
                *(float2*)(C + (size_t)r0 * ldc + c)       = make_float2(v00, v01);
                *(float2*)(C + (size_t)(r0 + 8) * ldc + c) = make_float2(v10, v11);
            }
        }
    }
}

// float -> half, 8 elems/thread
__global__ void __launch_bounds__(256)
f2h8(const float4* __restrict__ in, uint4* __restrict__ out, int n8)
{
    int i = blockIdx.x * 256 + threadIdx.x;
    if (i < n8) {
        float4 a = in[2 * i], b = in[2 * i + 1];
        __half2 h0 = __floats2half2_rn(a.x, a.y);
        __half2 h1 = __floats2half2_rn(a.z, a.w);
        __half2 h2 = __floats2half2_rn(b.x, b.y);
        __half2 h3 = __floats2half2_rn(b.z, b.w);
        uint4 o;
        o.x = *(unsigned*)&h0; o.y = *(unsigned*)&h1;
        o.z = *(unsigned*)&h2; o.w = *(unsigned*)&h3;
        out[i] = o;
    }
}

// out[c][r] = half(in[r][c]); in [R,C] float row-major
__global__ void __launch_bounds__(256)
transpose_f2h(const float* __restrict__ in, __half* __restrict__ out, int R, int C)
{
    __shared__ float t[32][33];
    int c0 = blockIdx.x * 32, r0 = blockIdx.y * 32;
    int tx = threadIdx.x, ty = threadIdx.y;
#pragma unroll
    for (int i = 0; i < 32; i += 8)
        t[ty + i][tx] = in[(size_t)(r0 + ty + i) * C + c0 + tx];
    __syncthreads();
#pragma unroll
    for (int i = 0; i < 32; i += 8)
        out[(size_t)(c0 + ty + i) * R + r0 + tx] = __float2half(t[tx][ty + i]);
}

// Vt[z][c][r] = V[z][r][c], V rows strided by ldin (view into QKV)
__global__ void __launch_bounds__(256)
transpose_h_strided(const __half* __restrict__ in, int ldin,
                    __half* __restrict__ out, int R, int C)
{
    __shared__ __half t[32][33];
    const __half* ip = in + (size_t)blockIdx.z * R * ldin;
    __half* op = out + (size_t)blockIdx.z * R * C;
    int c0 = blockIdx.x * 32, r0 = blockIdx.y * 32;
    int tx = threadIdx.x, ty = threadIdx.y;
#pragma unroll
    for (int i = 0; i < 32; i += 8)
        t[ty + i][tx] = ip[(size_t)(r0 + ty + i) * ldin + c0 + tx];
    __syncthreads();
#pragma unroll
    for (int i = 0; i < 32; i += 8)
        op[(size_t)(c0 + ty + i) * R + r0 + tx] = t[tx][ty + i];
}

// softmax over rows of 2048: fp32 in -> fp16 out
__global__ void __launch_bounds__(256)
softmax2048h(const float* __restrict__ S, __half* __restrict__ P)
{
    __shared__ float red_max[8];
    __shared__ float red_sum[8];
    const float* p = S + (size_t)blockIdx.x * 2048;
    __half* o = P + (size_t)blockIdx.x * 2048;
    const int t = threadIdx.x;

    float4 v0 = ((const float4*)p)[t];
    float4 v1 = ((const float4*)p)[t + 256];

    float m = fmaxf(fmaxf(fmaxf(v0.x, v0.y), fmaxf(v0.z, v0.w)),
                    fmaxf(fmaxf(v1.x, v1.y), fmaxf(v1.z, v1.w)));
#pragma unroll
    for (int off = 16; off; off >>= 1) m = fmaxf(m, __shfl_xor_sync(0xffffffffu, m, off));
    if ((t & 31) == 0) red_max[t >> 5] = m;
    __syncthreads();
    m = red_max[0];
#pragma unroll
    for (int w = 1; w < 8; w++) m = fmaxf(m, red_max[w]);

    v0.x = expf(v0.x - m); v0.y = expf(v0.y - m);
    v0.z = expf(v0.z - m); v0.w = expf(v0.w - m);
    v1.x = expf(v1.x - m); v1.y = expf(v1.y - m);
    v1.z = expf(v1.z - m); v1.w = expf(v1.w - m);

    float s = (v0.x + v0.y + v0.z + v0.w) + (v1.x + v1.y + v1.z + v1.w);
#pragma unroll
    for (int off = 16; off; off >>= 1) s += __shfl_xor_sync(0xffffffffu, s, off);
    if ((t & 31) == 0) red_sum[t >> 5] = s;
    __syncthreads();
    s = red_sum[0];
#pragma unroll
    for (int w = 1; w < 8; w++) s += red_sum[w];

    float inv = 1.0f / s;
    __half2 h0 = __floats2half2_rn(v0.x * inv, v0.y * inv);
    __half2 h1 = __floats2half2_rn(v0.z * inv, v0.w * inv);
    __half2 h2 = __floats2half2_rn(v1.x * inv, v1.y * inv);
    __half2 h3 = __floats2half2_rn(v1.z * inv, v1.w * inv);
    uint2 o0, o1;
    o0.x = *(unsigned*)&h0; o0.y = *(unsigned*)&h1;
    o1.x = *(unsigned*)&h2; o1.y = *(unsigned*)&h3;
    ((uint2*)o)[t]       = o0;
    ((uint2*)o)[t + 256] = o1;
}

extern "C" void kernel_launch(void* const* d_in, const int* in_sizes, int n_in,
                              void* d_out, int out_size)
{
    (void)in_sizes; (void)n_in; (void)out_size;
    const float* x  = (const float*)d_in[0];
    const float* Wq = (const float*)d_in[1];
    const float* bq = (const float*)d_in[2];
    const float* Wk = (const float*)d_in[3];
    const float* bk = (const float*)d_in[4];
    const float* Wv = (const float*)d_in[5];
    const float* bv = (const float*)d_in[6];
    float* out = (float*)d_out;

    __half *xh, *WT, *QKV, *Vt, *P;
    float *S, *biasAll;
    cudaGetSymbolAddress((void**)&xh,      g_xh);
    cudaGetSymbolAddress((void**)&WT,      g_WT);
    cudaGetSymbolAddress((void**)&biasAll, g_bias);
    cudaGetSymbolAddress((void**)&QKV,     g_QKV);
    cudaGetSymbolAddress((void**)&Vt,      g_Vt);
    cudaGetSymbolAddress((void**)&S,       g_S);
    cudaGetSymbolAddress((void**)&P,       g_P);

    cudaFuncSetAttribute(hgemm_nt<true,  true >,
                         cudaFuncAttributeMaxDynamicSharedMemorySize, SMEM_TOTAL_BYTES);
    cudaFuncSetAttribute(hgemm_nt<false, false>,
                         cudaFuncAttributeMaxDynamicSharedMemorySize, SMEM_TOTAL_BYTES);

    // 0) prep
    f2h8<<<ROWS * DIM / 8 / 256, 256>>>((const float4*)x, (uint4*)xh, ROWS * DIM / 8);
    {
        dim3 g(DIM / 32, DIM / 32, 1), b(32, 8);
        transpose_f2h<<<g, b>>>(Wq, WT,                         DIM, DIM);
        transpose_f2h<<<g, b>>>(Wk, WT + (size_t)DIM * DIM,     DIM, DIM);
        transpose_f2h<<<g, b>>>(Wv, WT + (size_t)2 * DIM * DIM, DIM, DIM);
    }
    cudaMemcpyAsync(biasAll,           bq, DIM * sizeof(float), cudaMemcpyDeviceToDevice);
    cudaMemcpyAsync(biasAll + DIM,     bk, DIM * sizeof(float), cudaMemcpyDeviceToDevice);
    cudaMemcpyAsync(biasAll + 2 * DIM, bv, DIM * sizeof(float), cudaMemcpyDeviceToDevice);

    // 1) fused QKV projection
    {
        dim3 g(QKVN / BN, ROWS / BM, 1);
        hgemm_nt<true, true><<<g, 256, SMEM_TOTAL_BYTES>>>(
            xh, DIM, WT, DIM, biasAll, QKV, QKVN, QKVN, DIM, 1.0f, 0, 0, 0);
    }

    // 2) V -> Vt per batch
    {
        dim3 g(DIM / 32, SEQ / 32, BATCH), b(32, 8);
        transpose_h_strided<<<g, b>>>(QKV + 2 * DIM, QKVN, Vt, SEQ, DIM);
    }

    // 3) scores = Q @ K^T / 32
    {
        dim3 g(SEQ / BN, SEQ / BM, BATCH);
        hgemm_nt<false, false><<<g, 256, SMEM_TOTAL_BYTES>>>(
            QKV, QKVN, QKV + DIM, QKVN, nullptr, S, SEQ,
            SEQ, DIM, 0.03125f,
            (long long)SEQ * QKVN, (long long)SEQ * QKVN, (long long)SEQ * SEQ);
    }

    // 4) softmax -> fp16 P
    softmax2048h<<<BATCH * SEQ, 256>>>(S, P);

    // 5) out = P @ Vt^T
    {
        dim3 g(DIM / BN, SEQ / BM, BATCH);
        hgemm_nt<false, false><<<g, 256, SMEM_TOTAL_BYTES>>>(
            P, SEQ, Vt, SEQ, nullptr, out, DIM,
            DIM, SEQ, 1.0f,
            (long long)SEQ * SEQ, (long long)SEQ * DIM, (long long)SEQ * DIM);
    }
}